// round 2
// baseline (speedup 1.0000x reference)
#include <cuda_runtime.h>
#include <math.h>
#include <math_constants.h>

// Problem constants
#define BB   2
#define SS   2048
#define HH   2048
#define NH   16
#define HD   128
#define MTOT (BB * SS)        // 4096
static __device__ __constant__ float d_scale = 0.08838834764831843f; // 1/sqrt(128)

// Scratch buffers (allocation-free: __device__ globals)
__device__ float g_q[(size_t)BB * SS * HH];
__device__ float g_k[(size_t)BB * SS * HH];
__device__ float g_v[(size_t)BB * SS * HH];
__device__ float g_ctx[(size_t)BB * SS * HH];

// ---------------------------------------------------------------------------
// SGEMM: C[M,N] = A[M,K] * B[N,K]^T   (all row-major, exact-multiple sizes)
// Block tile 128x128, K-tile 16, 256 threads, 8x8 per thread (split 4+4 with
// stride-64 halves so fragment loads are float4 and C stores are float4).
// ---------------------------------------------------------------------------
template <int M, int N, int K>
__global__ __launch_bounds__(256) void gemm_nt(const float* __restrict__ A,
                                               const float* __restrict__ Bm,
                                               float* __restrict__ C) {
    const int BM = 128, BN = 128, BK = 16;
    __shared__ float sA[BK][BM + 4];   // pad 4 keeps float4 alignment
    __shared__ float sB[BK][BN + 4];

    int tid = threadIdx.x;
    int tx = tid & 15;          // 0..15 -> N direction
    int ty = tid >> 4;          // 0..15 -> M direction
    int m0 = blockIdx.y * BM;
    int n0 = blockIdx.x * BN;

    float acc[8][8];
#pragma unroll
    for (int i = 0; i < 8; i++)
#pragma unroll
        for (int j = 0; j < 8; j++) acc[i][j] = 0.0f;

    for (int k0 = 0; k0 < K; k0 += BK) {
        // Load tiles (transposed into smem): 2048 elems each, 8 per thread
#pragma unroll
        for (int it = 0; it < 8; it++) {
            int flat = it * 256 + tid;
            int r = flat >> 4;        // 0..127
            int c = flat & 15;        // 0..15
            sA[c][r] = A[(size_t)(m0 + r) * K + k0 + c];
            sB[c][r] = Bm[(size_t)(n0 + r) * K + k0 + c];
        }
        __syncthreads();

#pragma unroll
        for (int kk = 0; kk < BK; kk++) {
            float4 a0 = *(const float4*)&sA[kk][ty * 4];
            float4 a1 = *(const float4*)&sA[kk][64 + ty * 4];
            float4 b0 = *(const float4*)&sB[kk][tx * 4];
            float4 b1 = *(const float4*)&sB[kk][64 + tx * 4];
            float a[8] = {a0.x, a0.y, a0.z, a0.w, a1.x, a1.y, a1.z, a1.w};
            float b[8] = {b0.x, b0.y, b0.z, b0.w, b1.x, b1.y, b1.z, b1.w};
#pragma unroll
            for (int i = 0; i < 8; i++)
#pragma unroll
                for (int j = 0; j < 8; j++) acc[i][j] += a[i] * b[j];
        }
        __syncthreads();
    }

    // Store: rows {ty*4+i, 64+ty*4+i}, cols {tx*4+j, 64+tx*4+j}, float4 stores
#pragma unroll
    for (int half_i = 0; half_i < 2; half_i++) {
#pragma unroll
        for (int i = 0; i < 4; i++) {
            int r = m0 + half_i * 64 + ty * 4 + i;
#pragma unroll
            for (int half_j = 0; half_j < 2; half_j++) {
                int cbase = n0 + half_j * 64 + tx * 4;
                float4 v;
                v.x = acc[half_i * 4 + i][half_j * 4 + 0];
                v.y = acc[half_i * 4 + i][half_j * 4 + 1];
                v.z = acc[half_i * 4 + i][half_j * 4 + 2];
                v.w = acc[half_i * 4 + i][half_j * 4 + 3];
                *(float4*)&C[(size_t)r * N + cbase] = v;
            }
        }
    }
}

// ---------------------------------------------------------------------------
// RoPE on g_q and g_k in place. One thread per (b,s,h,pair).
// position_ids is INT32 (JAX x64 disabled: jnp.int64 request silently -> int32).
// ---------------------------------------------------------------------------
__global__ __launch_bounds__(256) void rope_kernel(const int* __restrict__ pos_ids) {
    int idx = blockIdx.x * blockDim.x + threadIdx.x;
    const int total = BB * SS * NH * (HD / 2);
    if (idx >= total) return;
    int i = idx & 63;             // pair index 0..63
    int t = idx >> 6;
    int h = t & (NH - 1);
    t >>= 4;
    int s = t & (SS - 1);
    int b = t >> 11;

    int p = pos_ids[(size_t)b * SS + s];
    float inv_freq = 1.0f / powf(10000.0f, (float)(2 * i) / (float)HD);
    float ang = (float)p * inv_freq;
    float c, sn;
    sincosf(ang, &sn, &c);

    size_t base = ((size_t)(b * SS + s) * HH) + (size_t)h * HD + 2 * i;
    float x1 = g_q[base], x2 = g_q[base + 1];
    g_q[base]     = x1 * c - x2 * sn;
    g_q[base + 1] = x1 * sn + x2 * c;
    x1 = g_k[base]; x2 = g_k[base + 1];
    g_k[base]     = x1 * c - x2 * sn;
    g_k[base + 1] = x1 * sn + x2 * c;
}

// ---------------------------------------------------------------------------
// Flash attention (fp32, online softmax, causal). BM=BN=64, 256 threads.
// Thread (tx,ty): owns score rows ty*4+i (i<4), score cols j*16+tx (j<4),
// output cols cc*16+tx (cc<8). Causal tile skipping: j-tiles <= q-tile only.
// ---------------------------------------------------------------------------
__global__ __launch_bounds__(256) void flash_kernel() {
    const int BM = 64, BN = 64;
    __shared__ float sP[64 * 64];          // 16 KB  (probabilities)
    __shared__ float sU[2 * 64 * 33];      // 16.9 KB (Q+K chunks, reused for V)
    float* sQ = sU;
    float* sK = sU + 64 * 33;
    float* sV = sU;                        // aliases Q region during PV phase

    int tid = threadIdx.x;
    int tx = tid & 15;
    int ty = tid >> 4;
    int qt = blockIdx.x;                   // q tile (0..31)
    int h  = blockIdx.y;                   // head
    int b  = blockIdx.z;                   // batch
    int qbase = qt * BM;

    const float* qp = g_q + ((size_t)b * SS) * HH + (size_t)h * HD;
    const float* kp = g_k + ((size_t)b * SS) * HH + (size_t)h * HD;
    const float* vp = g_v + ((size_t)b * SS) * HH + (size_t)h * HD;

    float O[4][8];
#pragma unroll
    for (int i = 0; i < 4; i++)
#pragma unroll
        for (int c = 0; c < 8; c++) O[i][c] = 0.0f;
    float m_i[4] = {-CUDART_INF_F, -CUDART_INF_F, -CUDART_INF_F, -CUDART_INF_F};
    float l_i[4] = {0.0f, 0.0f, 0.0f, 0.0f};

    for (int jt = 0; jt <= qt; jt++) {
        int jbase = jt * BN;
        float Sreg[4][4];
#pragma unroll
        for (int i = 0; i < 4; i++)
#pragma unroll
            for (int j = 0; j < 4; j++) Sreg[i][j] = 0.0f;

        // ---- scores: S += Q_chunk @ K_chunk^T over 4 chunks of 32 dims ----
        for (int ch = 0; ch < 4; ch++) {
#pragma unroll
            for (int it = 0; it < 8; it++) {
                int flat = it * 256 + tid;
                int r = flat >> 5;       // 0..63
                int c = flat & 31;       // 0..31
                sQ[r * 33 + c] = qp[(size_t)(qbase + r) * HH + ch * 32 + c];
                sK[r * 33 + c] = kp[(size_t)(jbase + r) * HH + ch * 32 + c];
            }
            __syncthreads();
#pragma unroll
            for (int kk = 0; kk < 32; kk++) {
                float a[4], bb[4];
#pragma unroll
                for (int i = 0; i < 4; i++) a[i] = sQ[(ty * 4 + i) * 33 + kk];
#pragma unroll
                for (int j = 0; j < 4; j++) bb[j] = sK[(j * 16 + tx) * 33 + kk];
#pragma unroll
                for (int i = 0; i < 4; i++)
#pragma unroll
                    for (int j = 0; j < 4; j++) Sreg[i][j] += a[i] * bb[j];
            }
            __syncthreads();
        }

        // ---- scale + causal mask (only diagonal tile needs it) ----
        bool diag = (jt == qt);
#pragma unroll
        for (int i = 0; i < 4; i++) {
#pragma unroll
            for (int j = 0; j < 4; j++) {
                float v = Sreg[i][j] * d_scale;
                if (diag && (jbase + j * 16 + tx > qbase + ty * 4 + i)) v = -1e30f;
                Sreg[i][j] = v;
            }
        }

        // ---- online softmax per row ----
#pragma unroll
        for (int i = 0; i < 4; i++) {
            float mx = fmaxf(fmaxf(Sreg[i][0], Sreg[i][1]), fmaxf(Sreg[i][2], Sreg[i][3]));
#pragma unroll
            for (int off = 8; off >= 1; off >>= 1)
                mx = fmaxf(mx, __shfl_xor_sync(0xffffffffu, mx, off, 32));
            float m_new = fmaxf(m_i[i], mx);
            float alpha = __expf(m_i[i] - m_new);
            float rs = 0.0f;
#pragma unroll
            for (int j = 0; j < 4; j++) {
                float pp = __expf(Sreg[i][j] - m_new);
                Sreg[i][j] = pp;
                rs += pp;
            }
#pragma unroll
            for (int off = 8; off >= 1; off >>= 1)
                rs += __shfl_xor_sync(0xffffffffu, rs, off, 32);
            l_i[i] = l_i[i] * alpha + rs;
            m_i[i] = m_new;
#pragma unroll
            for (int c = 0; c < 8; c++) O[i][c] *= alpha;
#pragma unroll
            for (int j = 0; j < 4; j++)
                sP[(ty * 4 + i) * 64 + j * 16 + tx] = Sreg[i][j];
        }
        __syncthreads();

        // ---- O += P @ V, V in 4 chunks of 32 dims ----
        for (int ch = 0; ch < 4; ch++) {
#pragma unroll
            for (int it = 0; it < 8; it++) {
                int flat = it * 256 + tid;
                int r = flat >> 5;
                int c = flat & 31;
                sV[r * 33 + c] = vp[(size_t)(jbase + r) * HH + ch * 32 + c];
            }
            __syncthreads();
#pragma unroll
            for (int kk = 0; kk < 64; kk++) {
                float v0 = sV[kk * 33 + tx];
                float v1 = sV[kk * 33 + 16 + tx];
#pragma unroll
                for (int i = 0; i < 4; i++) {
                    float pp = sP[(ty * 4 + i) * 64 + kk];
                    O[i][2 * ch]     += pp * v0;
                    O[i][2 * ch + 1] += pp * v1;
                }
            }
            __syncthreads();
        }
    }

    // ---- epilogue: normalize and write ctx ----
    float* cp = g_ctx + ((size_t)b * SS) * HH + (size_t)h * HD;
#pragma unroll
    for (int i = 0; i < 4; i++) {
        float inv = 1.0f / l_i[i];
        size_t row = (size_t)(qbase + ty * 4 + i) * HH;
#pragma unroll
        for (int c = 0; c < 8; c++)
            cp[row + c * 16 + tx] = O[i][c] * inv;
    }
}

// ---------------------------------------------------------------------------
// Launch: QKV GEMMs -> RoPE -> flash attention -> output projection
// ---------------------------------------------------------------------------
extern "C" void kernel_launch(void* const* d_in, const int* in_sizes, int n_in,
                              void* d_out, int out_size) {
    const float* hidden = (const float*)d_in[0];
    const float* Wq = (const float*)d_in[1];
    const float* Wk = (const float*)d_in[2];
    const float* Wv = (const float*)d_in[3];
    const float* Wd = (const float*)d_in[4];
    // d_in[5] = attention_mask (bool, causal — implicit in kernel)
    const int* pos = (const int*)d_in[6];
    float* out = (float*)d_out;

    float *qptr, *kptr, *vptr, *cptr;
    cudaGetSymbolAddress((void**)&qptr, g_q);
    cudaGetSymbolAddress((void**)&kptr, g_k);
    cudaGetSymbolAddress((void**)&vptr, g_v);
    cudaGetSymbolAddress((void**)&cptr, g_ctx);

    dim3 gemm_grid(HH / 128, MTOT / 128);   // (16, 32)
    gemm_nt<MTOT, HH, HH><<<gemm_grid, 256>>>(hidden, Wq, qptr);
    gemm_nt<MTOT, HH, HH><<<gemm_grid, 256>>>(hidden, Wk, kptr);
    gemm_nt<MTOT, HH, HH><<<gemm_grid, 256>>>(hidden, Wv, vptr);

    int rope_total = BB * SS * NH * (HD / 2);
    rope_kernel<<<(rope_total + 255) / 256, 256>>>(pos);

    dim3 flash_grid(SS / 64, NH, BB);       // (32, 16, 2)
    flash_kernel<<<flash_grid, 256>>>();

    gemm_nt<MTOT, HH, HH><<<gemm_grid, 256>>>(cptr, Wd, out);
}

// round 3
// speedup vs baseline: 1.4718x; 1.4718x over previous
#include <cuda_runtime.h>
#include <math.h>
#include <math_constants.h>
#include <stdint.h>

// Problem constants
#define BB   2
#define SS   2048
#define HH   2048
#define NH   16
#define HD   128
#define MTOT (BB * SS)        // 4096
static __device__ __constant__ float d_scale = 0.08838834764831843f; // 1/sqrt(128)

// Scratch buffers (allocation-free: __device__ globals)
__device__ float g_q[(size_t)BB * SS * HH];
__device__ float g_k[(size_t)BB * SS * HH];
__device__ float g_v[(size_t)BB * SS * HH];
__device__ float g_ctx[(size_t)BB * SS * HH];

__device__ __forceinline__ uint32_t f2tf32(float x) {
    uint32_t r;
    asm("cvt.rna.tf32.f32 %0, %1;" : "=r"(r) : "f"(x));
    return r;
}

// ---------------------------------------------------------------------------
// TF32 tensor-core GEMM: C[M,N] = A[M,K] * B[N,K]^T  (row-major, exact tiles)
// Block 128x128x32, 8 warps (2x4), warp tile 64x32, mma.sync.m16n8k8.tf32.
// ---------------------------------------------------------------------------
template <int M, int N, int K>
__global__ __launch_bounds__(256, 2) void gemm_tf32(const float* __restrict__ A,
                                                    const float* __restrict__ Bm,
                                                    float* __restrict__ C) {
    __shared__ uint32_t sA[128][33];
    __shared__ uint32_t sB[128][33];

    const int tid  = threadIdx.x;
    const int lane = tid & 31;
    const int warp = tid >> 5;
    const int warpM = warp >> 2;        // 0..1  -> 64-row slab
    const int warpN = warp & 3;         // 0..3  -> 32-col slab
    const int gid = lane >> 2;          // 0..7
    const int tig = lane & 3;           // 0..3
    const int m0 = blockIdx.y * 128;
    const int n0 = blockIdx.x * 128;

    float c[4][4][4];                   // [mtile][ntile][frag]
#pragma unroll
    for (int i = 0; i < 4; i++)
#pragma unroll
        for (int j = 0; j < 4; j++)
#pragma unroll
            for (int r = 0; r < 4; r++) c[i][j][r] = 0.0f;

    for (int k0 = 0; k0 < K; k0 += 32) {
        // ---- load tiles (128 rows x 32 k) as float4, convert to tf32 ----
#pragma unroll
        for (int it = 0; it < 4; it++) {
            int flat = it * 256 + tid;
            int row = flat >> 3;
            int c4 = (flat & 7) * 4;
            float4 av = *(const float4*)&A[(size_t)(m0 + row) * K + k0 + c4];
            sA[row][c4 + 0] = f2tf32(av.x);
            sA[row][c4 + 1] = f2tf32(av.y);
            sA[row][c4 + 2] = f2tf32(av.z);
            sA[row][c4 + 3] = f2tf32(av.w);
            float4 bv = *(const float4*)&Bm[(size_t)(n0 + row) * K + k0 + c4];
            sB[row][c4 + 0] = f2tf32(bv.x);
            sB[row][c4 + 1] = f2tf32(bv.y);
            sB[row][c4 + 2] = f2tf32(bv.z);
            sB[row][c4 + 3] = f2tf32(bv.w);
        }
        __syncthreads();

#pragma unroll
        for (int ks = 0; ks < 4; ks++) {
            const int kc = ks * 8;
            uint32_t a[4][4];
#pragma unroll
            for (int i = 0; i < 4; i++) {
                int rb = warpM * 64 + i * 16 + gid;
                a[i][0] = sA[rb][kc + tig];
                a[i][1] = sA[rb + 8][kc + tig];
                a[i][2] = sA[rb][kc + tig + 4];
                a[i][3] = sA[rb + 8][kc + tig + 4];
            }
            uint32_t b[4][2];
#pragma unroll
            for (int j = 0; j < 4; j++) {
                int nb = warpN * 32 + j * 8 + gid;
                b[j][0] = sB[nb][kc + tig];
                b[j][1] = sB[nb][kc + tig + 4];
            }
#pragma unroll
            for (int i = 0; i < 4; i++)
#pragma unroll
                for (int j = 0; j < 4; j++) {
                    asm volatile(
                        "mma.sync.aligned.m16n8k8.row.col.f32.tf32.tf32.f32 "
                        "{%0,%1,%2,%3}, {%4,%5,%6,%7}, {%8,%9}, {%0,%1,%2,%3};"
                        : "+f"(c[i][j][0]), "+f"(c[i][j][1]),
                          "+f"(c[i][j][2]), "+f"(c[i][j][3])
                        : "r"(a[i][0]), "r"(a[i][1]), "r"(a[i][2]), "r"(a[i][3]),
                          "r"(b[j][0]), "r"(b[j][1]));
                }
        }
        __syncthreads();
    }

    // ---- store: rows gid/gid+8 per 16-row mtile, cols tig*2 pairs ----
#pragma unroll
    for (int i = 0; i < 4; i++) {
        int row0 = m0 + warpM * 64 + i * 16 + gid;
#pragma unroll
        for (int j = 0; j < 4; j++) {
            int col = n0 + warpN * 32 + j * 8 + tig * 2;
            *(float2*)&C[(size_t)row0 * N + col] = make_float2(c[i][j][0], c[i][j][1]);
            *(float2*)&C[(size_t)(row0 + 8) * N + col] = make_float2(c[i][j][2], c[i][j][3]);
        }
    }
}

// ---------------------------------------------------------------------------
// RoPE on g_q and g_k in place. One thread per (b,s,h,pair).
// position_ids is INT32 (JAX x64 disabled: int64 request silently -> int32).
// ---------------------------------------------------------------------------
__global__ __launch_bounds__(256) void rope_kernel(const int* __restrict__ pos_ids) {
    int idx = blockIdx.x * blockDim.x + threadIdx.x;
    const int total = BB * SS * NH * (HD / 2);
    if (idx >= total) return;
    int i = idx & 63;             // pair index 0..63
    int t = idx >> 6;
    int h = t & (NH - 1);
    t >>= 4;
    int s = t & (SS - 1);
    int b = t >> 11;

    int p = pos_ids[(size_t)b * SS + s];
    float inv_freq = 1.0f / powf(10000.0f, (float)(2 * i) / (float)HD);
    float ang = (float)p * inv_freq;
    float c, sn;
    sincosf(ang, &sn, &c);

    size_t base = ((size_t)(b * SS + s) * HH) + (size_t)h * HD + 2 * i;
    float x1 = g_q[base], x2 = g_q[base + 1];
    g_q[base]     = x1 * c - x2 * sn;
    g_q[base + 1] = x1 * sn + x2 * c;
    x1 = g_k[base]; x2 = g_k[base + 1];
    g_k[base]     = x1 * c - x2 * sn;
    g_k[base + 1] = x1 * sn + x2 * c;
}

// ---------------------------------------------------------------------------
// Flash attention (fp32, online softmax, causal). BM=BN=64, 256 threads.
// ---------------------------------------------------------------------------
__global__ __launch_bounds__(256) void flash_kernel() {
    const int BM = 64, BN = 64;
    __shared__ float sP[64 * 64];
    __shared__ float sU[2 * 64 * 33];
    float* sQ = sU;
    float* sK = sU + 64 * 33;
    float* sV = sU;

    int tid = threadIdx.x;
    int tx = tid & 15;
    int ty = tid >> 4;
    int qt = blockIdx.x;
    int h  = blockIdx.y;
    int b  = blockIdx.z;
    int qbase = qt * BM;

    const float* qp = g_q + ((size_t)b * SS) * HH + (size_t)h * HD;
    const float* kp = g_k + ((size_t)b * SS) * HH + (size_t)h * HD;
    const float* vp = g_v + ((size_t)b * SS) * HH + (size_t)h * HD;

    float O[4][8];
#pragma unroll
    for (int i = 0; i < 4; i++)
#pragma unroll
        for (int c = 0; c < 8; c++) O[i][c] = 0.0f;
    float m_i[4] = {-CUDART_INF_F, -CUDART_INF_F, -CUDART_INF_F, -CUDART_INF_F};
    float l_i[4] = {0.0f, 0.0f, 0.0f, 0.0f};

    for (int jt = 0; jt <= qt; jt++) {
        int jbase = jt * BN;
        float Sreg[4][4];
#pragma unroll
        for (int i = 0; i < 4; i++)
#pragma unroll
            for (int j = 0; j < 4; j++) Sreg[i][j] = 0.0f;

        for (int ch = 0; ch < 4; ch++) {
#pragma unroll
            for (int it = 0; it < 8; it++) {
                int flat = it * 256 + tid;
                int r = flat >> 5;
                int c = flat & 31;
                sQ[r * 33 + c] = qp[(size_t)(qbase + r) * HH + ch * 32 + c];
                sK[r * 33 + c] = kp[(size_t)(jbase + r) * HH + ch * 32 + c];
            }
            __syncthreads();
#pragma unroll
            for (int kk = 0; kk < 32; kk++) {
                float a[4], bb[4];
#pragma unroll
                for (int i = 0; i < 4; i++) a[i] = sQ[(ty * 4 + i) * 33 + kk];
#pragma unroll
                for (int j = 0; j < 4; j++) bb[j] = sK[(j * 16 + tx) * 33 + kk];
#pragma unroll
                for (int i = 0; i < 4; i++)
#pragma unroll
                    for (int j = 0; j < 4; j++) Sreg[i][j] += a[i] * bb[j];
            }
            __syncthreads();
        }

        bool diag = (jt == qt);
#pragma unroll
        for (int i = 0; i < 4; i++) {
#pragma unroll
            for (int j = 0; j < 4; j++) {
                float v = Sreg[i][j] * d_scale;
                if (diag && (jbase + j * 16 + tx > qbase + ty * 4 + i)) v = -1e30f;
                Sreg[i][j] = v;
            }
        }

#pragma unroll
        for (int i = 0; i < 4; i++) {
            float mx = fmaxf(fmaxf(Sreg[i][0], Sreg[i][1]), fmaxf(Sreg[i][2], Sreg[i][3]));
#pragma unroll
            for (int off = 8; off >= 1; off >>= 1)
                mx = fmaxf(mx, __shfl_xor_sync(0xffffffffu, mx, off, 32));
            float m_new = fmaxf(m_i[i], mx);
            float alpha = __expf(m_i[i] - m_new);
            float rs = 0.0f;
#pragma unroll
            for (int j = 0; j < 4; j++) {
                float pp = __expf(Sreg[i][j] - m_new);
                Sreg[i][j] = pp;
                rs += pp;
            }
#pragma unroll
            for (int off = 8; off >= 1; off >>= 1)
                rs += __shfl_xor_sync(0xffffffffu, rs, off, 32);
            l_i[i] = l_i[i] * alpha + rs;
            m_i[i] = m_new;
#pragma unroll
            for (int c = 0; c < 8; c++) O[i][c] *= alpha;
#pragma unroll
            for (int j = 0; j < 4; j++)
                sP[(ty * 4 + i) * 64 + j * 16 + tx] = Sreg[i][j];
        }
        __syncthreads();

        for (int ch = 0; ch < 4; ch++) {
#pragma unroll
            for (int it = 0; it < 8; it++) {
                int flat = it * 256 + tid;
                int r = flat >> 5;
                int c = flat & 31;
                sV[r * 33 + c] = vp[(size_t)(jbase + r) * HH + ch * 32 + c];
            }
            __syncthreads();
#pragma unroll
            for (int kk = 0; kk < 64; kk++) {
                float v0 = sV[kk * 33 + tx];
                float v1 = sV[kk * 33 + 16 + tx];
#pragma unroll
                for (int i = 0; i < 4; i++) {
                    float pp = sP[(ty * 4 + i) * 64 + kk];
                    O[i][2 * ch]     += pp * v0;
                    O[i][2 * ch + 1] += pp * v1;
                }
            }
            __syncthreads();
        }
    }

    float* cp = g_ctx + ((size_t)b * SS) * HH + (size_t)h * HD;
#pragma unroll
    for (int i = 0; i < 4; i++) {
        float inv = 1.0f / l_i[i];
        size_t row = (size_t)(qbase + ty * 4 + i) * HH;
#pragma unroll
        for (int c = 0; c < 8; c++)
            cp[row + c * 16 + tx] = O[i][c] * inv;
    }
}

// ---------------------------------------------------------------------------
// Launch: QKV GEMMs (tf32 MMA) -> RoPE -> flash attention -> output proj
// ---------------------------------------------------------------------------
extern "C" void kernel_launch(void* const* d_in, const int* in_sizes, int n_in,
                              void* d_out, int out_size) {
    const float* hidden = (const float*)d_in[0];
    const float* Wq = (const float*)d_in[1];
    const float* Wk = (const float*)d_in[2];
    const float* Wv = (const float*)d_in[3];
    const float* Wd = (const float*)d_in[4];
    // d_in[5] = attention_mask (bool, causal — implicit in kernel)
    const int* pos = (const int*)d_in[6];
    float* out = (float*)d_out;

    float *qptr, *kptr, *vptr, *cptr;
    cudaGetSymbolAddress((void**)&qptr, g_q);
    cudaGetSymbolAddress((void**)&kptr, g_k);
    cudaGetSymbolAddress((void**)&vptr, g_v);
    cudaGetSymbolAddress((void**)&cptr, g_ctx);

    dim3 gemm_grid(HH / 128, MTOT / 128);   // (16, 32)
    gemm_tf32<MTOT, HH, HH><<<gemm_grid, 256>>>(hidden, Wq, qptr);
    gemm_tf32<MTOT, HH, HH><<<gemm_grid, 256>>>(hidden, Wk, kptr);
    gemm_tf32<MTOT, HH, HH><<<gemm_grid, 256>>>(hidden, Wv, vptr);

    int rope_total = BB * SS * NH * (HD / 2);
    rope_kernel<<<(rope_total + 255) / 256, 256>>>(pos);

    dim3 flash_grid(SS / 64, NH, BB);       // (32, 16, 2)
    flash_kernel<<<flash_grid, 256>>>();

    gemm_tf32<MTOT, HH, HH><<<gemm_grid, 256>>>(cptr, Wd, out);
}

// round 4
// speedup vs baseline: 2.5625x; 1.7411x over previous
#include <cuda_runtime.h>
#include <math.h>
#include <math_constants.h>
#include <stdint.h>

#define BB   2
#define SS   2048
#define HH   2048
#define NH   16
#define HD   128
#define MTOT (BB * SS)
static __device__ __constant__ float d_scale = 0.08838834764831843f; // 1/sqrt(128)

__device__ float g_q[(size_t)BB * SS * HH];
__device__ float g_k[(size_t)BB * SS * HH];
__device__ float g_v[(size_t)BB * SS * HH];
__device__ float g_ctx[(size_t)BB * SS * HH];

__device__ __forceinline__ uint32_t f2tf32(float x) {
    uint32_t r;
    asm("cvt.rna.tf32.f32 %0, %1;" : "=r"(r) : "f"(x));
    return r;
}

__device__ __forceinline__ void mma_tf32(float& c0, float& c1, float& c2, float& c3,
                                         uint32_t a0, uint32_t a1, uint32_t a2, uint32_t a3,
                                         uint32_t b0, uint32_t b1) {
    asm volatile(
        "mma.sync.aligned.m16n8k8.row.col.f32.tf32.tf32.f32 "
        "{%0,%1,%2,%3}, {%4,%5,%6,%7}, {%8,%9}, {%0,%1,%2,%3};"
        : "+f"(c0), "+f"(c1), "+f"(c2), "+f"(c3)
        : "r"(a0), "r"(a1), "r"(a2), "r"(a3), "r"(b0), "r"(b1));
}

// ---------------------------------------------------------------------------
// TF32 GEMM: C[M,N] = A[M,K]*B[N,K]^T. Block 128x128x32, 8 warps (2x4),
// warp tile 64x32. k-permuted smem (pairs k,k+4 adjacent) -> LDS.64 fragments,
// stride 40 words -> conflict-free ((8g+2t) mod 32 distinct per phase).
// ---------------------------------------------------------------------------
template <int M, int N, int K>
__global__ __launch_bounds__(256, 2) void gemm_tf32(const float* __restrict__ A,
                                                    const float* __restrict__ Bm,
                                                    float* __restrict__ C) {
    __shared__ uint32_t sA[128][40];
    __shared__ uint32_t sB[128][40];

    const int tid  = threadIdx.x;
    const int lane = tid & 31;
    const int warp = tid >> 5;
    const int warpM = warp >> 2;
    const int warpN = warp & 3;
    const int gid = lane >> 2;
    const int tig = lane & 3;
    const int m0 = blockIdx.y * 128;
    const int n0 = blockIdx.x * 128;

    float c[4][4][4];
#pragma unroll
    for (int i = 0; i < 4; i++)
#pragma unroll
        for (int j = 0; j < 4; j++)
#pragma unroll
            for (int r = 0; r < 4; r++) c[i][j][r] = 0.0f;

    for (int k0 = 0; k0 < K; k0 += 32) {
#pragma unroll
        for (int it = 0; it < 4; it++) {
            int flat = it * 256 + tid;
            int row = flat >> 3;
            int c4 = (flat & 7) * 4;
            int base = c4 & ~7;
            int sub = (c4 >> 2) & 1;        // 0 for k%8 in [0,4), 1 for [4,8)
            float4 av = *(const float4*)&A[(size_t)(m0 + row) * K + k0 + c4];
            sA[row][base + 0 + sub] = f2tf32(av.x);
            sA[row][base + 2 + sub] = f2tf32(av.y);
            sA[row][base + 4 + sub] = f2tf32(av.z);
            sA[row][base + 6 + sub] = f2tf32(av.w);
            float4 bv = *(const float4*)&Bm[(size_t)(n0 + row) * K + k0 + c4];
            sB[row][base + 0 + sub] = f2tf32(bv.x);
            sB[row][base + 2 + sub] = f2tf32(bv.y);
            sB[row][base + 4 + sub] = f2tf32(bv.z);
            sB[row][base + 6 + sub] = f2tf32(bv.w);
        }
        __syncthreads();

#pragma unroll
        for (int ks = 0; ks < 4; ks++) {
            const int kc = ks * 8;          // group base (perm space == linear base)
            uint32_t a[4][4];
#pragma unroll
            for (int i = 0; i < 4; i++) {
                int rb = warpM * 64 + i * 16 + gid;
                uint2 lo = *(const uint2*)&sA[rb][kc + 2 * tig];
                uint2 hi = *(const uint2*)&sA[rb + 8][kc + 2 * tig];
                a[i][0] = lo.x; a[i][2] = lo.y;   // k=tig, k=tig+4
                a[i][1] = hi.x; a[i][3] = hi.y;
            }
            uint32_t b[4][2];
#pragma unroll
            for (int j = 0; j < 4; j++) {
                int nb = warpN * 32 + j * 8 + gid;
                uint2 bb = *(const uint2*)&sB[nb][kc + 2 * tig];
                b[j][0] = bb.x; b[j][1] = bb.y;
            }
#pragma unroll
            for (int i = 0; i < 4; i++)
#pragma unroll
                for (int j = 0; j < 4; j++)
                    mma_tf32(c[i][j][0], c[i][j][1], c[i][j][2], c[i][j][3],
                             a[i][0], a[i][1], a[i][2], a[i][3], b[j][0], b[j][1]);
        }
        __syncthreads();
    }

#pragma unroll
    for (int i = 0; i < 4; i++) {
        int row0 = m0 + warpM * 64 + i * 16 + gid;
#pragma unroll
        for (int j = 0; j < 4; j++) {
            int col = n0 + warpN * 32 + j * 8 + tig * 2;
            *(float2*)&C[(size_t)row0 * N + col] = make_float2(c[i][j][0], c[i][j][1]);
            *(float2*)&C[(size_t)(row0 + 8) * N + col] = make_float2(c[i][j][2], c[i][j][3]);
        }
    }
}

// ---------------------------------------------------------------------------
// RoPE on g_q/g_k in place; outputs rounded to tf32 grid (flash uses raw bits).
// ---------------------------------------------------------------------------
__global__ __launch_bounds__(256) void rope_kernel(const int* __restrict__ pos_ids) {
    int idx = blockIdx.x * blockDim.x + threadIdx.x;
    const int total = BB * SS * NH * (HD / 2);
    if (idx >= total) return;
    int i = idx & 63;
    int t = idx >> 6;
    int h = t & (NH - 1);
    t >>= 4;
    int s = t & (SS - 1);
    int b = t >> 11;

    int p = pos_ids[(size_t)b * SS + s];
    float inv_freq = 1.0f / powf(10000.0f, (float)(2 * i) / (float)HD);
    float ang = (float)p * inv_freq;
    float c, sn;
    sincosf(ang, &sn, &c);

    size_t base = ((size_t)(b * SS + s) * HH) + (size_t)h * HD + 2 * i;
    float x1 = g_q[base], x2 = g_q[base + 1];
    g_q[base]     = __uint_as_float(f2tf32(x1 * c - x2 * sn));
    g_q[base + 1] = __uint_as_float(f2tf32(x1 * sn + x2 * c));
    x1 = g_k[base]; x2 = g_k[base + 1];
    g_k[base]     = __uint_as_float(f2tf32(x1 * c - x2 * sn));
    g_k[base + 1] = __uint_as_float(f2tf32(x1 * sn + x2 * c));
}

// Round V to tf32 grid in place (vectorized).
__global__ __launch_bounds__(256) void vconv_kernel() {
    int idx = blockIdx.x * blockDim.x + threadIdx.x;
    float4* p = (float4*)g_v;
    float4 v = p[idx];
    v.x = __uint_as_float(f2tf32(v.x));
    v.y = __uint_as_float(f2tf32(v.y));
    v.z = __uint_as_float(f2tf32(v.z));
    v.w = __uint_as_float(f2tf32(v.w));
    p[idx] = v;
}

// ---------------------------------------------------------------------------
// TF32 tensor-core flash attention. BM=BN=64, 4 warps (128 thr), each warp
// owns 16 q-rows. Scores in register c-frags; softmax via width-4 shfl;
// P stored to smem as tf32; PV via MMA with V resident in smem.
// Strides: sQ/sK 36 ((4g+t)%32 distinct), sP 68, sV 132 -> conflict-free.
// ---------------------------------------------------------------------------
#define FQ_STR 36
#define FP_STR 68
#define FV_STR 132
#define FQ_OFF 0
#define FK_OFF (64 * FQ_STR)
#define FP_OFF (2 * 64 * FQ_STR)
#define FV_OFF (2 * 64 * FQ_STR + 64 * FP_STR)
#define FLASH_SMEM_FLOATS (2 * 64 * FQ_STR + 64 * FP_STR + 64 * FV_STR)

__global__ __launch_bounds__(128) void flash_tc_kernel() {
    extern __shared__ float sm[];
    float* sQ = sm + FQ_OFF;
    float* sK = sm + FK_OFF;
    float* sP = sm + FP_OFF;
    float* sV = sm + FV_OFF;

    const int tid = threadIdx.x;
    const int lane = tid & 31;
    const int warp = tid >> 5;          // 0..3, 16 q-rows each
    const int gid = lane >> 2;
    const int tig = lane & 3;
    const int qt = blockIdx.x;
    const int h  = blockIdx.y;
    const int b  = blockIdx.z;
    const int qbase = qt * 64;

    const float* qp = g_q + ((size_t)b * SS) * HH + (size_t)h * HD;
    const float* kp = g_k + ((size_t)b * SS) * HH + (size_t)h * HD;
    const float* vp = g_v + ((size_t)b * SS) * HH + (size_t)h * HD;

    const int r0 = warp * 16 + gid;     // local score row of c0/c1
    const int r1 = r0 + 8;              // local score row of c2/c3

    float o[16][4];                     // O accumulators: 16 hd n-tiles
#pragma unroll
    for (int j = 0; j < 16; j++)
#pragma unroll
        for (int r = 0; r < 4; r++) o[j][r] = 0.0f;
    float m0 = -CUDART_INF_F, m1 = -CUDART_INF_F;
    float l0 = 0.0f, l1 = 0.0f;

    for (int jt = 0; jt <= qt; jt++) {
        const int jbase = jt * 64;
        float s[8][4];
#pragma unroll
        for (int j = 0; j < 8; j++)
#pragma unroll
            for (int r = 0; r < 4; r++) s[j][r] = 0.0f;

        // ---------- Phase A: scores S = Q K^T over 4 chunks of 32 dims ----
        for (int ch = 0; ch < 4; ch++) {
#pragma unroll
            for (int it = 0; it < 4; it++) {
                int flat = it * 128 + tid;
                int row = flat >> 3;
                int c4 = (flat & 7) * 4;
                *(float4*)&sQ[row * FQ_STR + c4] =
                    *(const float4*)&qp[(size_t)(qbase + row) * HH + ch * 32 + c4];
                *(float4*)&sK[row * FQ_STR + c4] =
                    *(const float4*)&kp[(size_t)(jbase + row) * HH + ch * 32 + c4];
            }
            __syncthreads();
#pragma unroll
            for (int kc = 0; kc < 32; kc += 8) {
                uint32_t a0 = __float_as_uint(sQ[r0 * FQ_STR + kc + tig]);
                uint32_t a1 = __float_as_uint(sQ[r1 * FQ_STR + kc + tig]);
                uint32_t a2 = __float_as_uint(sQ[r0 * FQ_STR + kc + tig + 4]);
                uint32_t a3 = __float_as_uint(sQ[r1 * FQ_STR + kc + tig + 4]);
#pragma unroll
                for (int j = 0; j < 8; j++) {
                    int nb = j * 8 + gid;
                    uint32_t b0 = __float_as_uint(sK[nb * FQ_STR + kc + tig]);
                    uint32_t b1 = __float_as_uint(sK[nb * FQ_STR + kc + tig + 4]);
                    mma_tf32(s[j][0], s[j][1], s[j][2], s[j][3], a0, a1, a2, a3, b0, b1);
                }
            }
            __syncthreads();
        }

        // ---------- scale + causal mask ----------
        const bool diag = (jt == qt);
#pragma unroll
        for (int j = 0; j < 8; j++) {
            int col = jbase + j * 8 + tig * 2;
            s[j][0] *= d_scale; s[j][1] *= d_scale;
            s[j][2] *= d_scale; s[j][3] *= d_scale;
            if (diag) {
                int row_g0 = qbase + r0, row_g1 = qbase + r1;
                if (col     > row_g0) s[j][0] = -1e30f;
                if (col + 1 > row_g0) s[j][1] = -1e30f;
                if (col     > row_g1) s[j][2] = -1e30f;
                if (col + 1 > row_g1) s[j][3] = -1e30f;
            }
        }

        // ---------- online softmax (rows r0, r1; reduce over tig group) ----
        float mx0 = -CUDART_INF_F, mx1 = -CUDART_INF_F;
#pragma unroll
        for (int j = 0; j < 8; j++) {
            mx0 = fmaxf(mx0, fmaxf(s[j][0], s[j][1]));
            mx1 = fmaxf(mx1, fmaxf(s[j][2], s[j][3]));
        }
        mx0 = fmaxf(mx0, __shfl_xor_sync(0xffffffffu, mx0, 1));
        mx0 = fmaxf(mx0, __shfl_xor_sync(0xffffffffu, mx0, 2));
        mx1 = fmaxf(mx1, __shfl_xor_sync(0xffffffffu, mx1, 1));
        mx1 = fmaxf(mx1, __shfl_xor_sync(0xffffffffu, mx1, 2));
        float mn0 = fmaxf(m0, mx0), mn1 = fmaxf(m1, mx1);
        float al0 = __expf(m0 - mn0), al1 = __expf(m1 - mn1);
        float rs0 = 0.0f, rs1 = 0.0f;
#pragma unroll
        for (int j = 0; j < 8; j++) {
            s[j][0] = __expf(s[j][0] - mn0);
            s[j][1] = __expf(s[j][1] - mn0);
            s[j][2] = __expf(s[j][2] - mn1);
            s[j][3] = __expf(s[j][3] - mn1);
            rs0 += s[j][0] + s[j][1];
            rs1 += s[j][2] + s[j][3];
        }
        rs0 += __shfl_xor_sync(0xffffffffu, rs0, 1);
        rs0 += __shfl_xor_sync(0xffffffffu, rs0, 2);
        rs1 += __shfl_xor_sync(0xffffffffu, rs1, 1);
        rs1 += __shfl_xor_sync(0xffffffffu, rs1, 2);
        l0 = l0 * al0 + rs0;  m0 = mn0;
        l1 = l1 * al1 + rs1;  m1 = mn1;
#pragma unroll
        for (int j = 0; j < 16; j++) {
            o[j][0] *= al0; o[j][1] *= al0;
            o[j][2] *= al1; o[j][3] *= al1;
        }
        // store P (tf32 bits) to smem; each warp owns its 16 rows
#pragma unroll
        for (int j = 0; j < 8; j++) {
            int col = j * 8 + tig * 2;
            uint2 p0 = make_uint2(f2tf32(s[j][0]), f2tf32(s[j][1]));
            uint2 p1 = make_uint2(f2tf32(s[j][2]), f2tf32(s[j][3]));
            *(uint2*)&sP[r0 * FP_STR + col] = p0;
            *(uint2*)&sP[r1 * FP_STR + col] = p1;
        }
        __syncwarp();

        // ---------- Phase B: O += P @ V ----------
#pragma unroll
        for (int it = 0; it < 16; it++) {
            int flat = it * 128 + tid;
            int row = flat >> 5;
            int c4 = (flat & 31) * 4;
            *(float4*)&sV[row * FV_STR + c4] =
                *(const float4*)&vp[(size_t)(jbase + row) * HH + c4];
        }
        __syncthreads();
#pragma unroll
        for (int kc = 0; kc < 64; kc += 8) {
            uint32_t a0 = __float_as_uint(sP[r0 * FP_STR + kc + tig]);
            uint32_t a1 = __float_as_uint(sP[r1 * FP_STR + kc + tig]);
            uint32_t a2 = __float_as_uint(sP[r0 * FP_STR + kc + tig + 4]);
            uint32_t a3 = __float_as_uint(sP[r1 * FP_STR + kc + tig + 4]);
#pragma unroll
            for (int j = 0; j < 16; j++) {
                int n = j * 8 + gid;
                uint32_t b0 = __float_as_uint(sV[(kc + tig) * FV_STR + n]);
                uint32_t b1 = __float_as_uint(sV[(kc + tig + 4) * FV_STR + n]);
                mma_tf32(o[j][0], o[j][1], o[j][2], o[j][3], a0, a1, a2, a3, b0, b1);
            }
        }
        __syncthreads();
    }

    // ---------- epilogue ----------
    float* cp = g_ctx + ((size_t)b * SS) * HH + (size_t)h * HD;
    float inv0 = 1.0f / l0, inv1 = 1.0f / l1;
    size_t grow0 = (size_t)(qbase + r0) * HH;
    size_t grow1 = (size_t)(qbase + r1) * HH;
#pragma unroll
    for (int j = 0; j < 16; j++) {
        int col = j * 8 + tig * 2;
        *(float2*)&cp[grow0 + col] = make_float2(o[j][0] * inv0, o[j][1] * inv0);
        *(float2*)&cp[grow1 + col] = make_float2(o[j][2] * inv1, o[j][3] * inv1);
    }
}

// ---------------------------------------------------------------------------
extern "C" void kernel_launch(void* const* d_in, const int* in_sizes, int n_in,
                              void* d_out, int out_size) {
    const float* hidden = (const float*)d_in[0];
    const float* Wq = (const float*)d_in[1];
    const float* Wk = (const float*)d_in[2];
    const float* Wv = (const float*)d_in[3];
    const float* Wd = (const float*)d_in[4];
    const int* pos = (const int*)d_in[6];
    float* out = (float*)d_out;

    float *qptr, *kptr, *vptr, *cptr;
    cudaGetSymbolAddress((void**)&qptr, g_q);
    cudaGetSymbolAddress((void**)&kptr, g_k);
    cudaGetSymbolAddress((void**)&vptr, g_v);
    cudaGetSymbolAddress((void**)&cptr, g_ctx);

    static bool attr_set = false;
    if (!attr_set) {
        cudaFuncSetAttribute(flash_tc_kernel,
                             cudaFuncAttributeMaxDynamicSharedMemorySize,
                             FLASH_SMEM_FLOATS * (int)sizeof(float));
        attr_set = true;
    }

    dim3 gemm_grid(HH / 128, MTOT / 128);
    gemm_tf32<MTOT, HH, HH><<<gemm_grid, 256>>>(hidden, Wq, qptr);
    gemm_tf32<MTOT, HH, HH><<<gemm_grid, 256>>>(hidden, Wk, kptr);
    gemm_tf32<MTOT, HH, HH><<<gemm_grid, 256>>>(hidden, Wv, vptr);

    int rope_total = BB * SS * NH * (HD / 2);
    rope_kernel<<<(rope_total + 255) / 256, 256>>>(pos);
    vconv_kernel<<<(BB * SS * HH / 4) / 256, 256>>>();

    dim3 flash_grid(SS / 64, NH, BB);
    flash_tc_kernel<<<flash_grid, 128, FLASH_SMEM_FLOATS * sizeof(float)>>>();

    gemm_tf32<MTOT, HH, HH><<<gemm_grid, 256>>>(cptr, Wd, out);
}

// round 5
// speedup vs baseline: 3.4382x; 1.3417x over previous
#include <cuda_runtime.h>
#include <math.h>
#include <math_constants.h>
#include <stdint.h>

#define BB   2
#define SS   2048
#define HH   2048
#define NH   16
#define HD   128
#define MTOT (BB * SS)
static __device__ __constant__ float d_scale = 0.08838834764831843f; // 1/sqrt(128)

// Scratch (allocation-free: __device__ globals)
__device__ float g_q[(size_t)BB * SS * HH];
__device__ float g_k[(size_t)BB * SS * HH];
__device__ float g_v[(size_t)BB * SS * HH];
__device__ float g_ctx[(size_t)BB * SS * HH];
__device__ float g_hid[(size_t)MTOT * HH];
__device__ float g_wq[(size_t)HH * HH];
__device__ float g_wk[(size_t)HH * HH];
__device__ float g_wv[(size_t)HH * HH];
__device__ float g_wd[(size_t)HH * HH];

__device__ __forceinline__ uint32_t f2tf32(float x) {
    uint32_t r;
    asm("cvt.rna.tf32.f32 %0, %1;" : "=r"(r) : "f"(x));
    return r;
}

__device__ __forceinline__ void mma_tf32(float& c0, float& c1, float& c2, float& c3,
                                         uint32_t a0, uint32_t a1, uint32_t a2, uint32_t a3,
                                         uint32_t b0, uint32_t b1) {
    asm volatile(
        "mma.sync.aligned.m16n8k8.row.col.f32.tf32.tf32.f32 "
        "{%0,%1,%2,%3}, {%4,%5,%6,%7}, {%8,%9}, {%0,%1,%2,%3};"
        : "+f"(c0), "+f"(c1), "+f"(c2), "+f"(c3)
        : "r"(a0), "r"(a1), "r"(a2), "r"(a3), "r"(b0), "r"(b1));
}

// ---------------------------------------------------------------------------
// Round fp32 -> tf32 grid (RNA), vectorized copy.
// ---------------------------------------------------------------------------
__global__ __launch_bounds__(256) void round_tf32_kernel(const float4* __restrict__ src,
                                                         float4* __restrict__ dst, int n4) {
    int i = blockIdx.x * blockDim.x + threadIdx.x;
    if (i >= n4) return;
    float4 v = src[i];
    v.x = __uint_as_float(f2tf32(v.x));
    v.y = __uint_as_float(f2tf32(v.y));
    v.z = __uint_as_float(f2tf32(v.z));
    v.w = __uint_as_float(f2tf32(v.w));
    dst[i] = v;
}

// ---------------------------------------------------------------------------
// Pipelined TF32 GEMM: C[M,N] = A[M,K]*B[N,K]^T. Inputs pre-rounded to tf32.
// Block 128x128x32, 8 warps (2x4), warp tile 64x32. cp.async double buffer,
// XOR-swizzled smem (16B chunk c stored at c^(row&7)): conflict-free for both
// the cp.async stores and the scalar fragment loads (bank = 4*(c^g)+t).
// Dynamic smem 64KB, 2 CTAs/SM.
// ---------------------------------------------------------------------------
template <int M, int N, int K, bool ROUND_OUT>
__global__ __launch_bounds__(256, 2) void gemm_pipe(const float* __restrict__ A,
                                                    const float* __restrict__ Bm,
                                                    float* __restrict__ C) {
    extern __shared__ float smp[];
    float* sA = smp;            // [2][128][32]
    float* sB = smp + 8192;

    const int tid  = threadIdx.x;
    const int lane = tid & 31;
    const int warp = tid >> 5;
    const int warpM = warp >> 2;
    const int warpN = warp & 3;
    const int gid = lane >> 2;
    const int tig = lane & 3;
    const int m0 = blockIdx.y * 128;
    const int n0 = blockIdx.x * 128;

    float c[4][4][4];
#pragma unroll
    for (int i = 0; i < 4; i++)
#pragma unroll
        for (int j = 0; j < 4; j++)
#pragma unroll
            for (int r = 0; r < 4; r++) c[i][j][r] = 0.0f;

    // cp.async issue of one 128x32 tile pair into buffer `buf` at k-offset k0
    auto issue_tile = [&](int buf, int k0) {
#pragma unroll
        for (int it = 0; it < 4; it++) {
            int flat = it * 256 + tid;
            int row = flat >> 3;
            int g = flat & 7;
            int sw = (g ^ (row & 7)) * 4;
            uint32_t da = (uint32_t)__cvta_generic_to_shared(&sA[buf * 4096 + row * 32 + sw]);
            const float* pa = &A[(size_t)(m0 + row) * K + k0 + g * 4];
            asm volatile("cp.async.cg.shared.global [%0], [%1], 16;" :: "r"(da), "l"(pa));
            uint32_t db = (uint32_t)__cvta_generic_to_shared(&sB[buf * 4096 + row * 32 + sw]);
            const float* pb = &Bm[(size_t)(n0 + row) * K + k0 + g * 4];
            asm volatile("cp.async.cg.shared.global [%0], [%1], 16;" :: "r"(db), "l"(pb));
        }
        asm volatile("cp.async.commit_group;");
    };

    issue_tile(0, 0);
    for (int k0 = 0; k0 < K; k0 += 32) {
        int buf = (k0 >> 5) & 1;
        if (k0 + 32 < K) {
            issue_tile(buf ^ 1, k0 + 32);
            asm volatile("cp.async.wait_group 1;");
        } else {
            asm volatile("cp.async.wait_group 0;");
        }
        __syncthreads();

        const float* cA = sA + buf * 4096;
        const float* cB = sB + buf * 4096;
#pragma unroll
        for (int ks = 0; ks < 4; ks++) {
            const int c0g = ks * 2;           // 16B-chunk index of k-group base
            uint32_t a[4][4];
#pragma unroll
            for (int i = 0; i < 4; i++) {
                int rb = warpM * 64 + i * 16 + gid;       // rb&7 == gid
                int sw0 = ((c0g) ^ gid) * 4 + tig;
                int sw1 = ((c0g + 1) ^ gid) * 4 + tig;
                a[i][0] = __float_as_uint(cA[rb * 32 + sw0]);
                a[i][2] = __float_as_uint(cA[rb * 32 + sw1]);
                a[i][1] = __float_as_uint(cA[(rb + 8) * 32 + sw0]);
                a[i][3] = __float_as_uint(cA[(rb + 8) * 32 + sw1]);
            }
            uint32_t b[4][2];
#pragma unroll
            for (int j = 0; j < 4; j++) {
                int nb = warpN * 32 + j * 8 + gid;        // nb&7 == gid
                int sw0 = ((c0g) ^ gid) * 4 + tig;
                int sw1 = ((c0g + 1) ^ gid) * 4 + tig;
                b[j][0] = __float_as_uint(cB[nb * 32 + sw0]);
                b[j][1] = __float_as_uint(cB[nb * 32 + sw1]);
            }
#pragma unroll
            for (int i = 0; i < 4; i++)
#pragma unroll
                for (int j = 0; j < 4; j++)
                    mma_tf32(c[i][j][0], c[i][j][1], c[i][j][2], c[i][j][3],
                             a[i][0], a[i][1], a[i][2], a[i][3], b[j][0], b[j][1]);
        }
        __syncthreads();
    }

#pragma unroll
    for (int i = 0; i < 4; i++) {
        int row0 = m0 + warpM * 64 + i * 16 + gid;
#pragma unroll
        for (int j = 0; j < 4; j++) {
            int col = n0 + warpN * 32 + j * 8 + tig * 2;
            float2 v0, v1;
            if (ROUND_OUT) {
                v0 = make_float2(__uint_as_float(f2tf32(c[i][j][0])),
                                 __uint_as_float(f2tf32(c[i][j][1])));
                v1 = make_float2(__uint_as_float(f2tf32(c[i][j][2])),
                                 __uint_as_float(f2tf32(c[i][j][3])));
            } else {
                v0 = make_float2(c[i][j][0], c[i][j][1]);
                v1 = make_float2(c[i][j][2], c[i][j][3]);
            }
            *(float2*)&C[(size_t)row0 * N + col] = v0;
            *(float2*)&C[(size_t)(row0 + 8) * N + col] = v1;
        }
    }
}

// ---------------------------------------------------------------------------
// RoPE on g_q/g_k in place; outputs rounded to tf32 grid.
// position_ids is INT32 (JAX x64 disabled).
// ---------------------------------------------------------------------------
__global__ __launch_bounds__(256) void rope_kernel(const int* __restrict__ pos_ids) {
    int idx = blockIdx.x * blockDim.x + threadIdx.x;
    const int total = BB * SS * NH * (HD / 2);
    if (idx >= total) return;
    int i = idx & 63;
    int t = idx >> 6;
    int h = t & (NH - 1);
    t >>= 4;
    int s = t & (SS - 1);
    int b = t >> 11;

    int p = pos_ids[(size_t)b * SS + s];
    float inv_freq = 1.0f / powf(10000.0f, (float)(2 * i) / (float)HD);
    float ang = (float)p * inv_freq;
    float c, sn;
    sincosf(ang, &sn, &c);

    size_t base = ((size_t)(b * SS + s) * HH) + (size_t)h * HD + 2 * i;
    float x1 = g_q[base], x2 = g_q[base + 1];
    g_q[base]     = __uint_as_float(f2tf32(x1 * c - x2 * sn));
    g_q[base + 1] = __uint_as_float(f2tf32(x1 * sn + x2 * c));
    x1 = g_k[base]; x2 = g_k[base + 1];
    g_k[base]     = __uint_as_float(f2tf32(x1 * c - x2 * sn));
    g_k[base + 1] = __uint_as_float(f2tf32(x1 * sn + x2 * c));
}

// ---------------------------------------------------------------------------
// TF32 tensor-core flash attention. BM=BN=64, 4 warps; warp owns 16 q-rows.
// Epilogue rounds ctx to tf32 grid (feeds final pre-rounded GEMM).
// ---------------------------------------------------------------------------
#define FQ_STR 36
#define FP_STR 68
#define FV_STR 132
#define FQ_OFF 0
#define FK_OFF (64 * FQ_STR)
#define FP_OFF (2 * 64 * FQ_STR)
#define FV_OFF (2 * 64 * FQ_STR + 64 * FP_STR)
#define FLASH_SMEM_FLOATS (2 * 64 * FQ_STR + 64 * FP_STR + 64 * FV_STR)

__global__ __launch_bounds__(128) void flash_tc_kernel() {
    extern __shared__ float sm[];
    float* sQ = sm + FQ_OFF;
    float* sK = sm + FK_OFF;
    float* sP = sm + FP_OFF;
    float* sV = sm + FV_OFF;

    const int tid = threadIdx.x;
    const int lane = tid & 31;
    const int warp = tid >> 5;
    const int gid = lane >> 2;
    const int tig = lane & 3;
    const int qt = blockIdx.x;
    const int h  = blockIdx.y;
    const int b  = blockIdx.z;
    const int qbase = qt * 64;

    const float* qp = g_q + ((size_t)b * SS) * HH + (size_t)h * HD;
    const float* kp = g_k + ((size_t)b * SS) * HH + (size_t)h * HD;
    const float* vp = g_v + ((size_t)b * SS) * HH + (size_t)h * HD;

    const int r0 = warp * 16 + gid;
    const int r1 = r0 + 8;

    float o[16][4];
#pragma unroll
    for (int j = 0; j < 16; j++)
#pragma unroll
        for (int r = 0; r < 4; r++) o[j][r] = 0.0f;
    float m0 = -CUDART_INF_F, m1 = -CUDART_INF_F;
    float l0 = 0.0f, l1 = 0.0f;

    for (int jt = 0; jt <= qt; jt++) {
        const int jbase = jt * 64;
        float s[8][4];
#pragma unroll
        for (int j = 0; j < 8; j++)
#pragma unroll
            for (int r = 0; r < 4; r++) s[j][r] = 0.0f;

        for (int ch = 0; ch < 4; ch++) {
#pragma unroll
            for (int it = 0; it < 4; it++) {
                int flat = it * 128 + tid;
                int row = flat >> 3;
                int c4 = (flat & 7) * 4;
                *(float4*)&sQ[row * FQ_STR + c4] =
                    *(const float4*)&qp[(size_t)(qbase + row) * HH + ch * 32 + c4];
                *(float4*)&sK[row * FQ_STR + c4] =
                    *(const float4*)&kp[(size_t)(jbase + row) * HH + ch * 32 + c4];
            }
            __syncthreads();
#pragma unroll
            for (int kc = 0; kc < 32; kc += 8) {
                uint32_t a0 = __float_as_uint(sQ[r0 * FQ_STR + kc + tig]);
                uint32_t a1 = __float_as_uint(sQ[r1 * FQ_STR + kc + tig]);
                uint32_t a2 = __float_as_uint(sQ[r0 * FQ_STR + kc + tig + 4]);
                uint32_t a3 = __float_as_uint(sQ[r1 * FQ_STR + kc + tig + 4]);
#pragma unroll
                for (int j = 0; j < 8; j++) {
                    int nb = j * 8 + gid;
                    uint32_t b0 = __float_as_uint(sK[nb * FQ_STR + kc + tig]);
                    uint32_t b1 = __float_as_uint(sK[nb * FQ_STR + kc + tig + 4]);
                    mma_tf32(s[j][0], s[j][1], s[j][2], s[j][3], a0, a1, a2, a3, b0, b1);
                }
            }
            __syncthreads();
        }

        const bool diag = (jt == qt);
#pragma unroll
        for (int j = 0; j < 8; j++) {
            int col = jbase + j * 8 + tig * 2;
            s[j][0] *= d_scale; s[j][1] *= d_scale;
            s[j][2] *= d_scale; s[j][3] *= d_scale;
            if (diag) {
                int row_g0 = qbase + r0, row_g1 = qbase + r1;
                if (col     > row_g0) s[j][0] = -1e30f;
                if (col + 1 > row_g0) s[j][1] = -1e30f;
                if (col     > row_g1) s[j][2] = -1e30f;
                if (col + 1 > row_g1) s[j][3] = -1e30f;
            }
        }

        float mx0 = -CUDART_INF_F, mx1 = -CUDART_INF_F;
#pragma unroll
        for (int j = 0; j < 8; j++) {
            mx0 = fmaxf(mx0, fmaxf(s[j][0], s[j][1]));
            mx1 = fmaxf(mx1, fmaxf(s[j][2], s[j][3]));
        }
        mx0 = fmaxf(mx0, __shfl_xor_sync(0xffffffffu, mx0, 1));
        mx0 = fmaxf(mx0, __shfl_xor_sync(0xffffffffu, mx0, 2));
        mx1 = fmaxf(mx1, __shfl_xor_sync(0xffffffffu, mx1, 1));
        mx1 = fmaxf(mx1, __shfl_xor_sync(0xffffffffu, mx1, 2));
        float mn0 = fmaxf(m0, mx0), mn1 = fmaxf(m1, mx1);
        float al0 = __expf(m0 - mn0), al1 = __expf(m1 - mn1);
        float rs0 = 0.0f, rs1 = 0.0f;
#pragma unroll
        for (int j = 0; j < 8; j++) {
            s[j][0] = __expf(s[j][0] - mn0);
            s[j][1] = __expf(s[j][1] - mn0);
            s[j][2] = __expf(s[j][2] - mn1);
            s[j][3] = __expf(s[j][3] - mn1);
            rs0 += s[j][0] + s[j][1];
            rs1 += s[j][2] + s[j][3];
        }
        rs0 += __shfl_xor_sync(0xffffffffu, rs0, 1);
        rs0 += __shfl_xor_sync(0xffffffffu, rs0, 2);
        rs1 += __shfl_xor_sync(0xffffffffu, rs1, 1);
        rs1 += __shfl_xor_sync(0xffffffffu, rs1, 2);
        l0 = l0 * al0 + rs0;  m0 = mn0;
        l1 = l1 * al1 + rs1;  m1 = mn1;
#pragma unroll
        for (int j = 0; j < 16; j++) {
            o[j][0] *= al0; o[j][1] *= al0;
            o[j][2] *= al1; o[j][3] *= al1;
        }
#pragma unroll
        for (int j = 0; j < 8; j++) {
            int col = j * 8 + tig * 2;
            uint2 p0 = make_uint2(f2tf32(s[j][0]), f2tf32(s[j][1]));
            uint2 p1 = make_uint2(f2tf32(s[j][2]), f2tf32(s[j][3]));
            *(uint2*)&sP[r0 * FP_STR + col] = p0;
            *(uint2*)&sP[r1 * FP_STR + col] = p1;
        }
        __syncwarp();

#pragma unroll
        for (int it = 0; it < 16; it++) {
            int flat = it * 128 + tid;
            int row = flat >> 5;
            int c4 = (flat & 31) * 4;
            *(float4*)&sV[row * FV_STR + c4] =
                *(const float4*)&vp[(size_t)(jbase + row) * HH + c4];
        }
        __syncthreads();
#pragma unroll
        for (int kc = 0; kc < 64; kc += 8) {
            uint32_t a0 = __float_as_uint(sP[r0 * FP_STR + kc + tig]);
            uint32_t a1 = __float_as_uint(sP[r1 * FP_STR + kc + tig]);
            uint32_t a2 = __float_as_uint(sP[r0 * FP_STR + kc + tig + 4]);
            uint32_t a3 = __float_as_uint(sP[r1 * FP_STR + kc + tig + 4]);
#pragma unroll
            for (int j = 0; j < 16; j++) {
                int n = j * 8 + gid;
                uint32_t b0 = __float_as_uint(sV[(kc + tig) * FV_STR + n]);
                uint32_t b1 = __float_as_uint(sV[(kc + tig + 4) * FV_STR + n]);
                mma_tf32(o[j][0], o[j][1], o[j][2], o[j][3], a0, a1, a2, a3, b0, b1);
            }
        }
        __syncthreads();
    }

    float* cp = g_ctx + ((size_t)b * SS) * HH + (size_t)h * HD;
    float inv0 = 1.0f / l0, inv1 = 1.0f / l1;
    size_t grow0 = (size_t)(qbase + r0) * HH;
    size_t grow1 = (size_t)(qbase + r1) * HH;
#pragma unroll
    for (int j = 0; j < 16; j++) {
        int col = j * 8 + tig * 2;
        *(float2*)&cp[grow0 + col] =
            make_float2(__uint_as_float(f2tf32(o[j][0] * inv0)),
                        __uint_as_float(f2tf32(o[j][1] * inv0)));
        *(float2*)&cp[grow1 + col] =
            make_float2(__uint_as_float(f2tf32(o[j][2] * inv1)),
                        __uint_as_float(f2tf32(o[j][3] * inv1)));
    }
}

// ---------------------------------------------------------------------------
extern "C" void kernel_launch(void* const* d_in, const int* in_sizes, int n_in,
                              void* d_out, int out_size) {
    const float* hidden = (const float*)d_in[0];
    const float* Wq = (const float*)d_in[1];
    const float* Wk = (const float*)d_in[2];
    const float* Wv = (const float*)d_in[3];
    const float* Wd = (const float*)d_in[4];
    const int* pos = (const int*)d_in[6];
    float* out = (float*)d_out;

    float *qptr, *kptr, *vptr, *cptr;
    float *hptr, *wqp, *wkp, *wvp, *wdp;
    cudaGetSymbolAddress((void**)&qptr, g_q);
    cudaGetSymbolAddress((void**)&kptr, g_k);
    cudaGetSymbolAddress((void**)&vptr, g_v);
    cudaGetSymbolAddress((void**)&cptr, g_ctx);
    cudaGetSymbolAddress((void**)&hptr, g_hid);
    cudaGetSymbolAddress((void**)&wqp, g_wq);
    cudaGetSymbolAddress((void**)&wkp, g_wk);
    cudaGetSymbolAddress((void**)&wvp, g_wv);
    cudaGetSymbolAddress((void**)&wdp, g_wd);

    const int GEMM_SMEM = 2 * 2 * 128 * 32 * (int)sizeof(float); // 64 KB
    cudaFuncSetAttribute(gemm_pipe<MTOT, HH, HH, false>,
                         cudaFuncAttributeMaxDynamicSharedMemorySize, GEMM_SMEM);
    cudaFuncSetAttribute(gemm_pipe<MTOT, HH, HH, true>,
                         cudaFuncAttributeMaxDynamicSharedMemorySize, GEMM_SMEM);
    cudaFuncSetAttribute(flash_tc_kernel,
                         cudaFuncAttributeMaxDynamicSharedMemorySize,
                         FLASH_SMEM_FLOATS * (int)sizeof(float));

    // Pre-round all GEMM inputs to the tf32 grid
    int nh4 = MTOT * HH / 4, nw4 = HH * HH / 4;
    round_tf32_kernel<<<(nh4 + 255) / 256, 256>>>((const float4*)hidden, (float4*)hptr, nh4);
    round_tf32_kernel<<<(nw4 + 255) / 256, 256>>>((const float4*)Wq, (float4*)wqp, nw4);
    round_tf32_kernel<<<(nw4 + 255) / 256, 256>>>((const float4*)Wk, (float4*)wkp, nw4);
    round_tf32_kernel<<<(nw4 + 255) / 256, 256>>>((const float4*)Wv, (float4*)wvp, nw4);
    round_tf32_kernel<<<(nw4 + 255) / 256, 256>>>((const float4*)Wd, (float4*)wdp, nw4);

    dim3 gemm_grid(HH / 128, MTOT / 128);
    gemm_pipe<MTOT, HH, HH, false><<<gemm_grid, 256, GEMM_SMEM>>>(hptr, wqp, qptr);
    gemm_pipe<MTOT, HH, HH, false><<<gemm_grid, 256, GEMM_SMEM>>>(hptr, wkp, kptr);
    gemm_pipe<MTOT, HH, HH, true ><<<gemm_grid, 256, GEMM_SMEM>>>(hptr, wvp, vptr);

    int rope_total = BB * SS * NH * (HD / 2);
    rope_kernel<<<(rope_total + 255) / 256, 256>>>(pos);

    dim3 flash_grid(SS / 64, NH, BB);
    flash_tc_kernel<<<flash_grid, 128, FLASH_SMEM_FLOATS * sizeof(float)>>>();

    gemm_pipe<MTOT, HH, HH, false><<<gemm_grid, 256, GEMM_SMEM>>>(cptr, wdp, out);
}

// round 8
// speedup vs baseline: 7.8081x; 2.2710x over previous
#include <cuda_runtime.h>
#include <cuda_fp16.h>
#include <math.h>
#include <math_constants.h>
#include <stdint.h>

#define BB   2
#define SS   2048
#define HH   2048
#define NH   16
#define HD   128
#define MTOT (BB * SS)
static __device__ __constant__ float d_scale = 0.08838834764831843f; // 1/sqrt(128)

// Scratch (allocation-free: __device__ globals) — all fp16 intermediates
__device__ __half g_q[(size_t)BB * SS * HH];
__device__ __half g_k[(size_t)BB * SS * HH];
__device__ __half g_v[(size_t)BB * SS * HH];
__device__ __half g_vt[(size_t)BB * NH * HD * SS];   // [b][h][hd][s]
__device__ __half g_ctx[(size_t)BB * SS * HH];
__device__ __half g_hid[(size_t)MTOT * HH];
__device__ __half g_wq[(size_t)HH * HH];
__device__ __half g_wk[(size_t)HH * HH];
__device__ __half g_wv[(size_t)HH * HH];
__device__ __half g_wd[(size_t)HH * HH];

__device__ __forceinline__ void mma_f16(float& c0, float& c1, float& c2, float& c3,
                                        uint32_t a0, uint32_t a1, uint32_t a2, uint32_t a3,
                                        uint32_t b0, uint32_t b1) {
    asm volatile(
        "mma.sync.aligned.m16n8k16.row.col.f32.f16.f16.f32 "
        "{%0,%1,%2,%3}, {%4,%5,%6,%7}, {%8,%9}, {%0,%1,%2,%3};"
        : "+f"(c0), "+f"(c1), "+f"(c2), "+f"(c3)
        : "r"(a0), "r"(a1), "r"(a2), "r"(a3), "r"(b0), "r"(b1));
}

__device__ __forceinline__ uint32_t pack_h2(float lo, float hi) {
    __half2 h = __floats2half2_rn(lo, hi);
    return *(uint32_t*)&h;
}

// ---------------------------------------------------------------------------
// fp32 -> fp16 conversion (RNE), vectorized.
// ---------------------------------------------------------------------------
__global__ __launch_bounds__(256) void to_half_kernel(const float4* __restrict__ src,
                                                      uint2* __restrict__ dst, int n4) {
    int i = blockIdx.x * blockDim.x + threadIdx.x;
    if (i >= n4) return;
    float4 v = src[i];
    uint2 o;
    o.x = pack_h2(v.x, v.y);
    o.y = pack_h2(v.z, v.w);
    dst[i] = o;
}

// ---------------------------------------------------------------------------
// FP16 tensor GEMM: C[M,N] = A[M,K]*B[N,K]^T (A,B fp16, accum fp32).
// Block 128x128x64, 8 warps (2x4), warp tile 64x32, m16n8k16.
// cp.async double buffer; rows are 128B (64 halves); XOR swizzle on 16B
// chunks (ch ^ (row&7)) -> conflict-free stores and fragment loads.
// ---------------------------------------------------------------------------
#define GH_TILE   16384                         // bytes per 128x64-half tile
#define GH_SMEM   (4 * GH_TILE)                 // A0,A1,B0,B1 = 64 KB

template <int M, int N, int K, bool OUT_HALF>
__global__ __launch_bounds__(256, 2) void gemm_f16(const __half* __restrict__ A,
                                                   const __half* __restrict__ Bm,
                                                   void* __restrict__ Cout) {
    extern __shared__ char smem[];
    char* sA = smem;                            // [2][128][128B]
    char* sB = smem + 2 * GH_TILE;

    const int tid  = threadIdx.x;
    const int lane = tid & 31;
    const int warp = tid >> 5;
    const int warpM = warp >> 2;
    const int warpN = warp & 3;
    const int gid = lane >> 2;
    const int tig = lane & 3;
    const int m0 = blockIdx.y * 128;
    const int n0 = blockIdx.x * 128;

    float c[4][4][4];
#pragma unroll
    for (int i = 0; i < 4; i++)
#pragma unroll
        for (int j = 0; j < 4; j++)
#pragma unroll
            for (int r = 0; r < 4; r++) c[i][j][r] = 0.0f;

    auto issue_tile = [&](int buf, int k0) {
#pragma unroll
        for (int it = 0; it < 4; it++) {
            int flat = it * 256 + tid;          // 0..1023
            int row = flat >> 3;
            int ch = flat & 7;
            int sw = (ch ^ (row & 7)) * 16;
            uint32_t da = (uint32_t)__cvta_generic_to_shared(sA + buf * GH_TILE + row * 128 + sw);
            const __half* pa = &A[(size_t)(m0 + row) * K + k0 + ch * 8];
            asm volatile("cp.async.cg.shared.global [%0], [%1], 16;" :: "r"(da), "l"(pa));
            uint32_t db = (uint32_t)__cvta_generic_to_shared(sB + buf * GH_TILE + row * 128 + sw);
            const __half* pb = &Bm[(size_t)(n0 + row) * K + k0 + ch * 8];
            asm volatile("cp.async.cg.shared.global [%0], [%1], 16;" :: "r"(db), "l"(pb));
        }
        asm volatile("cp.async.commit_group;");
    };

    issue_tile(0, 0);
    for (int k0 = 0; k0 < K; k0 += 64) {
        int buf = (k0 >> 6) & 1;
        if (k0 + 64 < K) {
            issue_tile(buf ^ 1, k0 + 64);
            asm volatile("cp.async.wait_group 1;");
        } else {
            asm volatile("cp.async.wait_group 0;");
        }
        __syncthreads();

        const char* cA = sA + buf * GH_TILE;
        const char* cB = sB + buf * GH_TILE;
#pragma unroll
        for (int ks = 0; ks < 4; ks++) {        // k-steps of 16
            uint32_t a[4][4];
#pragma unroll
            for (int i = 0; i < 4; i++) {
                int r = warpM * 64 + i * 16 + gid;      // r&7 == gid (i*16, warpM*64 mult of 8)
                int rs = r * 128;
                int c0 = ((2 * ks) ^ gid) * 16 + 4 * tig;
                int c1 = ((2 * ks + 1) ^ gid) * 16 + 4 * tig;
                a[i][0] = *(const uint32_t*)(cA + rs + c0);
                a[i][2] = *(const uint32_t*)(cA + rs + c1);
                a[i][1] = *(const uint32_t*)(cA + rs + 1024 + c0);   // row r+8
                a[i][3] = *(const uint32_t*)(cA + rs + 1024 + c1);
            }
            uint32_t b[4][2];
#pragma unroll
            for (int j = 0; j < 4; j++) {
                int n = warpN * 32 + j * 8 + gid;
                int ns = n * 128;
                b[j][0] = *(const uint32_t*)(cB + ns + (((2 * ks) ^ gid) * 16 + 4 * tig));
                b[j][1] = *(const uint32_t*)(cB + ns + (((2 * ks + 1) ^ gid) * 16 + 4 * tig));
            }
#pragma unroll
            for (int i = 0; i < 4; i++)
#pragma unroll
                for (int j = 0; j < 4; j++)
                    mma_f16(c[i][j][0], c[i][j][1], c[i][j][2], c[i][j][3],
                            a[i][0], a[i][1], a[i][2], a[i][3], b[j][0], b[j][1]);
        }
        __syncthreads();
    }

#pragma unroll
    for (int i = 0; i < 4; i++) {
        int row0 = m0 + warpM * 64 + i * 16 + gid;
#pragma unroll
        for (int j = 0; j < 4; j++) {
            int col = n0 + warpN * 32 + j * 8 + tig * 2;
            if (OUT_HALF) {
                __half* C = (__half*)Cout;
                *(uint32_t*)&C[(size_t)row0 * N + col] = pack_h2(c[i][j][0], c[i][j][1]);
                *(uint32_t*)&C[(size_t)(row0 + 8) * N + col] = pack_h2(c[i][j][2], c[i][j][3]);
            } else {
                float* C = (float*)Cout;
                *(float2*)&C[(size_t)row0 * N + col] = make_float2(c[i][j][0], c[i][j][1]);
                *(float2*)&C[(size_t)(row0 + 8) * N + col] = make_float2(c[i][j][2], c[i][j][3]);
            }
        }
    }
}

// ---------------------------------------------------------------------------
// RoPE on g_q/g_k (fp16) in place. position_ids INT32.
// ---------------------------------------------------------------------------
__global__ __launch_bounds__(256) void rope_kernel(const int* __restrict__ pos_ids) {
    int idx = blockIdx.x * blockDim.x + threadIdx.x;
    const int total = BB * SS * NH * (HD / 2);
    if (idx >= total) return;
    int i = idx & 63;
    int t = idx >> 6;
    int h = t & (NH - 1);
    t >>= 4;
    int s = t & (SS - 1);
    int b = t >> 11;

    int p = pos_ids[(size_t)b * SS + s];
    float inv_freq = 1.0f / powf(10000.0f, (float)(2 * i) / (float)HD);
    float ang = (float)p * inv_freq;
    float c, sn;
    sincosf(ang, &sn, &c);

    size_t base = ((size_t)(b * SS + s) * HH) + (size_t)h * HD + 2 * i;
    __half2 q = *(__half2*)&g_q[base];
    float x1 = __low2float(q), x2 = __high2float(q);
    *(__half2*)&g_q[base] = __floats2half2_rn(x1 * c - x2 * sn, x1 * sn + x2 * c);
    __half2 k = *(__half2*)&g_k[base];
    x1 = __low2float(k); x2 = __high2float(k);
    *(__half2*)&g_k[base] = __floats2half2_rn(x1 * c - x2 * sn, x1 * sn + x2 * c);
}

// ---------------------------------------------------------------------------
// V transpose: g_v[b,s,h,hd] -> g_vt[b,h,hd,s]  (32x32 fp16 tiles)
// ---------------------------------------------------------------------------
__global__ __launch_bounds__(256) void vtrans_kernel() {
    __shared__ __half tile[32][33];
    const int bh = blockIdx.z;                    // b*16+h
    const int s0 = blockIdx.x * 32;
    const int hd0 = blockIdx.y * 32;
    const int tx = threadIdx.x & 31;
    const int ty = threadIdx.x >> 5;              // 0..7
    const int b = bh >> 4, h = bh & 15;
#pragma unroll
    for (int i = 0; i < 4; i++) {
        int sr = ty + i * 8;
        tile[sr][tx] = g_v[((size_t)(b * SS + s0 + sr)) * HH + h * HD + hd0 + tx];
    }
    __syncthreads();
#pragma unroll
    for (int i = 0; i < 4; i++) {
        int hr = ty + i * 8;
        g_vt[((size_t)(bh * HD + hd0 + hr)) * SS + s0 + tx] = tile[tx][hr];
    }
}

// ---------------------------------------------------------------------------
// FP16 tensor flash attention. BM=BN=64, 4 warps; warp owns 16 q-rows.
// Q tile (64x128h) resident across the jt loop; K and V^T loaded per jt.
// Strides (halves): sQ/sK 136, sP 72, sVt 72 -> conflict-free frag reads.
// ---------------------------------------------------------------------------
#define FQ_STR 136
#define FP_STR 72
#define FV_STR 72
#define FQ_OFF 0
#define FK_OFF (64 * FQ_STR)
#define FP_OFF (2 * 64 * FQ_STR)
#define FV_OFF (2 * 64 * FQ_STR + 64 * FP_STR)
#define FLASH_SMEM_HALVES (2 * 64 * FQ_STR + 64 * FP_STR + 128 * FV_STR)

__global__ __launch_bounds__(128) void flash_f16_kernel() {
    extern __shared__ __half sh[];
    __half* sQ = sh + FQ_OFF;
    __half* sK = sh + FK_OFF;
    __half* sP = sh + FP_OFF;
    __half* sVt = sh + FV_OFF;

    const int tid = threadIdx.x;
    const int lane = tid & 31;
    const int warp = tid >> 5;
    const int gid = lane >> 2;
    const int tig = lane & 3;
    const int qt = blockIdx.x;
    const int h  = blockIdx.y;
    const int b  = blockIdx.z;
    const int qbase = qt * 64;

    const __half* qp = g_q + ((size_t)b * SS) * HH + (size_t)h * HD;
    const __half* kp = g_k + ((size_t)b * SS) * HH + (size_t)h * HD;
    const __half* vtp = g_vt + ((size_t)(b * NH + h)) * HD * SS;

    const int r0 = warp * 16 + gid;
    const int r1 = r0 + 8;

    // Load Q tile once: 64 rows x 16 chunks (8 halves)
#pragma unroll
    for (int it = 0; it < 8; it++) {
        int flat = it * 128 + tid;
        int row = flat >> 4;
        int ch = flat & 15;
        *(uint4*)&sQ[row * FQ_STR + ch * 8] =
            *(const uint4*)&qp[(size_t)(qbase + row) * HH + ch * 8];
    }

    float o[16][4];
#pragma unroll
    for (int j = 0; j < 16; j++)
#pragma unroll
        for (int r = 0; r < 4; r++) o[j][r] = 0.0f;
    float m0 = -CUDART_INF_F, m1 = -CUDART_INF_F;
    float l0 = 0.0f, l1 = 0.0f;

    for (int jt = 0; jt <= qt; jt++) {
        const int jbase = jt * 64;
        __syncthreads();                         // prior PV done with sK/sVt
        // K tile: 64 rows x 16 chunks; V^T tile: 128 rows x 8 chunks
#pragma unroll
        for (int it = 0; it < 8; it++) {
            int flat = it * 128 + tid;
            int row = flat >> 4;
            int ch = flat & 15;
            *(uint4*)&sK[row * FQ_STR + ch * 8] =
                *(const uint4*)&kp[(size_t)(jbase + row) * HH + ch * 8];
            int vrow = flat >> 3;
            int vch = flat & 7;
            *(uint4*)&sVt[vrow * FV_STR + vch * 8] =
                *(const uint4*)&vtp[(size_t)vrow * SS + jbase + vch * 8];
        }
        __syncthreads();

        // ---- scores S = Q K^T : 8 k-steps of 16 ----
        float s[8][4];
#pragma unroll
        for (int j = 0; j < 8; j++)
#pragma unroll
            for (int r = 0; r < 4; r++) s[j][r] = 0.0f;
#pragma unroll
        for (int ks = 0; ks < 8; ks++) {
            const int k0 = ks * 16;
            uint32_t a0 = *(uint32_t*)&sQ[r0 * FQ_STR + k0 + 2 * tig];
            uint32_t a1 = *(uint32_t*)&sQ[r1 * FQ_STR + k0 + 2 * tig];
            uint32_t a2 = *(uint32_t*)&sQ[r0 * FQ_STR + k0 + 8 + 2 * tig];
            uint32_t a3 = *(uint32_t*)&sQ[r1 * FQ_STR + k0 + 8 + 2 * tig];
#pragma unroll
            for (int j = 0; j < 8; j++) {
                int n = j * 8 + gid;
                uint32_t b0 = *(uint32_t*)&sK[n * FQ_STR + k0 + 2 * tig];
                uint32_t b1 = *(uint32_t*)&sK[n * FQ_STR + k0 + 8 + 2 * tig];
                mma_f16(s[j][0], s[j][1], s[j][2], s[j][3], a0, a1, a2, a3, b0, b1);
            }
        }

        // ---- scale + causal mask ----
        const bool diag = (jt == qt);
#pragma unroll
        for (int j = 0; j < 8; j++) {
            int col = jbase + j * 8 + tig * 2;
            s[j][0] *= d_scale; s[j][1] *= d_scale;
            s[j][2] *= d_scale; s[j][3] *= d_scale;
            if (diag) {
                int rg0 = qbase + r0, rg1 = qbase + r1;
                if (col     > rg0) s[j][0] = -1e30f;
                if (col + 1 > rg0) s[j][1] = -1e30f;
                if (col     > rg1) s[j][2] = -1e30f;
                if (col + 1 > rg1) s[j][3] = -1e30f;
            }
        }

        // ---- online softmax ----
        float mx0 = -CUDART_INF_F, mx1 = -CUDART_INF_F;
#pragma unroll
        for (int j = 0; j < 8; j++) {
            mx0 = fmaxf(mx0, fmaxf(s[j][0], s[j][1]));
            mx1 = fmaxf(mx1, fmaxf(s[j][2], s[j][3]));
        }
        mx0 = fmaxf(mx0, __shfl_xor_sync(0xffffffffu, mx0, 1));
        mx0 = fmaxf(mx0, __shfl_xor_sync(0xffffffffu, mx0, 2));
        mx1 = fmaxf(mx1, __shfl_xor_sync(0xffffffffu, mx1, 1));
        mx1 = fmaxf(mx1, __shfl_xor_sync(0xffffffffu, mx1, 2));
        float mn0 = fmaxf(m0, mx0), mn1 = fmaxf(m1, mx1);
        float al0 = __expf(m0 - mn0), al1 = __expf(m1 - mn1);
        float rs0 = 0.0f, rs1 = 0.0f;
#pragma unroll
        for (int j = 0; j < 8; j++) {
            s[j][0] = __expf(s[j][0] - mn0);
            s[j][1] = __expf(s[j][1] - mn0);
            s[j][2] = __expf(s[j][2] - mn1);
            s[j][3] = __expf(s[j][3] - mn1);
            rs0 += s[j][0] + s[j][1];
            rs1 += s[j][2] + s[j][3];
        }
        rs0 += __shfl_xor_sync(0xffffffffu, rs0, 1);
        rs0 += __shfl_xor_sync(0xffffffffu, rs0, 2);
        rs1 += __shfl_xor_sync(0xffffffffu, rs1, 1);
        rs1 += __shfl_xor_sync(0xffffffffu, rs1, 2);
        l0 = l0 * al0 + rs0;  m0 = mn0;
        l1 = l1 * al1 + rs1;  m1 = mn1;
#pragma unroll
        for (int j = 0; j < 16; j++) {
            o[j][0] *= al0; o[j][1] *= al0;
            o[j][2] *= al1; o[j][3] *= al1;
        }
        // store P as fp16 (each warp owns its 16 rows)
#pragma unroll
        for (int j = 0; j < 8; j++) {
            int col = j * 8 + tig * 2;
            *(uint32_t*)&sP[r0 * FP_STR + col] = pack_h2(s[j][0], s[j][1]);
            *(uint32_t*)&sP[r1 * FP_STR + col] = pack_h2(s[j][2], s[j][3]);
        }
        __syncwarp();

        // ---- O += P @ V : 4 k-steps of 16, 16 n-tiles ----
#pragma unroll
        for (int ks = 0; ks < 4; ks++) {
            const int k0 = ks * 16;
            uint32_t a0 = *(uint32_t*)&sP[r0 * FP_STR + k0 + 2 * tig];
            uint32_t a1 = *(uint32_t*)&sP[r1 * FP_STR + k0 + 2 * tig];
            uint32_t a2 = *(uint32_t*)&sP[r0 * FP_STR + k0 + 8 + 2 * tig];
            uint32_t a3 = *(uint32_t*)&sP[r1 * FP_STR + k0 + 8 + 2 * tig];
#pragma unroll
            for (int j = 0; j < 16; j++) {
                int n = j * 8 + gid;
                uint32_t b0 = *(uint32_t*)&sVt[n * FV_STR + k0 + 2 * tig];
                uint32_t b1 = *(uint32_t*)&sVt[n * FV_STR + k0 + 8 + 2 * tig];
                mma_f16(o[j][0], o[j][1], o[j][2], o[j][3], a0, a1, a2, a3, b0, b1);
            }
        }
    }

    // ---- epilogue: normalize, write ctx (fp16) ----
    __half* cp = g_ctx + ((size_t)b * SS) * HH + (size_t)h * HD;
    float inv0 = 1.0f / l0, inv1 = 1.0f / l1;
    size_t grow0 = (size_t)(qbase + r0) * HH;
    size_t grow1 = (size_t)(qbase + r1) * HH;
#pragma unroll
    for (int j = 0; j < 16; j++) {
        int col = j * 8 + tig * 2;
        *(uint32_t*)&cp[grow0 + col] = pack_h2(o[j][0] * inv0, o[j][1] * inv0);
        *(uint32_t*)&cp[grow1 + col] = pack_h2(o[j][2] * inv1, o[j][3] * inv1);
    }
}

// ---------------------------------------------------------------------------
extern "C" void kernel_launch(void* const* d_in, const int* in_sizes, int n_in,
                              void* d_out, int out_size) {
    const float* hidden = (const float*)d_in[0];
    const float* Wq = (const float*)d_in[1];
    const float* Wk = (const float*)d_in[2];
    const float* Wv = (const float*)d_in[3];
    const float* Wd = (const float*)d_in[4];
    const int* pos = (const int*)d_in[6];
    float* out = (float*)d_out;

    __half *qptr, *kptr, *vptr, *cptr, *hptr, *wqp, *wkp, *wvp, *wdp;
    cudaGetSymbolAddress((void**)&qptr, g_q);
    cudaGetSymbolAddress((void**)&kptr, g_k);
    cudaGetSymbolAddress((void**)&vptr, g_v);
    cudaGetSymbolAddress((void**)&cptr, g_ctx);
    cudaGetSymbolAddress((void**)&hptr, g_hid);
    cudaGetSymbolAddress((void**)&wqp, g_wq);
    cudaGetSymbolAddress((void**)&wkp, g_wk);
    cudaGetSymbolAddress((void**)&wvp, g_wv);
    cudaGetSymbolAddress((void**)&wdp, g_wd);

    cudaFuncSetAttribute(gemm_f16<MTOT, HH, HH, true>,
                         cudaFuncAttributeMaxDynamicSharedMemorySize, GH_SMEM);
    cudaFuncSetAttribute(gemm_f16<MTOT, HH, HH, false>,
                         cudaFuncAttributeMaxDynamicSharedMemorySize, GH_SMEM);
    cudaFuncSetAttribute(flash_f16_kernel,
                         cudaFuncAttributeMaxDynamicSharedMemorySize,
                         FLASH_SMEM_HALVES * (int)sizeof(__half));

    // fp32 -> fp16 input conversion
    int nh4 = MTOT * HH / 4, nw4 = HH * HH / 4;
    to_half_kernel<<<(nh4 + 255) / 256, 256>>>((const float4*)hidden, (uint2*)hptr, nh4);
    to_half_kernel<<<(nw4 + 255) / 256, 256>>>((const float4*)Wq, (uint2*)wqp, nw4);
    to_half_kernel<<<(nw4 + 255) / 256, 256>>>((const float4*)Wk, (uint2*)wkp, nw4);
    to_half_kernel<<<(nw4 + 255) / 256, 256>>>((const float4*)Wv, (uint2*)wvp, nw4);
    to_half_kernel<<<(nw4 + 255) / 256, 256>>>((const float4*)Wd, (uint2*)wdp, nw4);

    dim3 gemm_grid(HH / 128, MTOT / 128);   // (16, 32)
    gemm_f16<MTOT, HH, HH, true><<<gemm_grid, 256, GH_SMEM>>>(hptr, wqp, qptr);
    gemm_f16<MTOT, HH, HH, true><<<gemm_grid, 256, GH_SMEM>>>(hptr, wkp, kptr);
    gemm_f16<MTOT, HH, HH, true><<<gemm_grid, 256, GH_SMEM>>>(hptr, wvp, vptr);

    int rope_total = BB * SS * NH * (HD / 2);
    rope_kernel<<<(rope_total + 255) / 256, 256>>>(pos);

    dim3 vt_grid(SS / 32, HD / 32, BB * NH);
    vtrans_kernel<<<vt_grid, 256>>>();

    dim3 flash_grid(SS / 64, NH, BB);
    flash_f16_kernel<<<flash_grid, 128, FLASH_SMEM_HALVES * sizeof(__half)>>>();

    gemm_f16<MTOT, HH, HH, false><<<gemm_grid, 256, GH_SMEM>>>(cptr, wdp, out);
}

// round 10
// speedup vs baseline: 8.2908x; 1.0618x over previous
#include <cuda_runtime.h>
#include <cuda_fp16.h>
#include <math.h>
#include <math_constants.h>
#include <stdint.h>

#define BB   2
#define SS   2048
#define HH   2048
#define NH   16
#define HD   128
#define MTOT (BB * SS)
static __device__ __constant__ float d_scale = 0.08838834764831843f; // 1/sqrt(128)

// Scratch (allocation-free: __device__ globals) — all fp16 intermediates
__device__ __half g_q[(size_t)BB * SS * HH];
__device__ __half g_k[(size_t)BB * SS * HH];
__device__ __half g_vt[(size_t)BB * NH * HD * SS];   // [b][h][hd][s]
__device__ __half g_ctx[(size_t)BB * SS * HH];
__device__ __half g_hid[(size_t)MTOT * HH];
__device__ __half g_wq[(size_t)HH * HH];
__device__ __half g_wk[(size_t)HH * HH];
__device__ __half g_wv[(size_t)HH * HH];
__device__ __half g_wd[(size_t)HH * HH];

__device__ __forceinline__ void mma_f16(float& c0, float& c1, float& c2, float& c3,
                                        uint32_t a0, uint32_t a1, uint32_t a2, uint32_t a3,
                                        uint32_t b0, uint32_t b1) {
    asm volatile(
        "mma.sync.aligned.m16n8k16.row.col.f32.f16.f16.f32 "
        "{%0,%1,%2,%3}, {%4,%5,%6,%7}, {%8,%9}, {%0,%1,%2,%3};"
        : "+f"(c0), "+f"(c1), "+f"(c2), "+f"(c3)
        : "r"(a0), "r"(a1), "r"(a2), "r"(a3), "r"(b0), "r"(b1));
}

__device__ __forceinline__ uint32_t pack_h2(float lo, float hi) {
    __half2 h = __floats2half2_rn(lo, hi);
    return *(uint32_t*)&h;
}

// ---------------------------------------------------------------------------
// Combined fp32 -> fp16 conversion: z-slice 0,1 = hidden halves, 2..5 = W*.
// ---------------------------------------------------------------------------
__global__ __launch_bounds__(256) void conv_all_kernel(
        const float4* __restrict__ hid, const float4* __restrict__ wq,
        const float4* __restrict__ wk, const float4* __restrict__ wv,
        const float4* __restrict__ wd, int n4) {
    int i = blockIdx.x * blockDim.x + threadIdx.x;
    if (i >= n4) return;
    int z = blockIdx.z;
    const float4* src;
    uint2* dst;
    switch (z) {
        case 0: src = hid;       dst = (uint2*)g_hid;        break;
        case 1: src = hid + n4;  dst = (uint2*)g_hid + n4;   break;
        case 2: src = wq;        dst = (uint2*)g_wq;         break;
        case 3: src = wk;        dst = (uint2*)g_wk;         break;
        case 4: src = wv;        dst = (uint2*)g_wv;         break;
        default: src = wd;       dst = (uint2*)g_wd;         break;
    }
    float4 v = src[i];
    uint2 o;
    o.x = pack_h2(v.x, v.y);
    o.y = pack_h2(v.z, v.w);
    dst[i] = o;
}

// ---------------------------------------------------------------------------
// FP16 tensor GEMM: C[M,N] = A[M,K]*B[N,K]^T (A,B fp16, accum fp32).
// Block 128x128x64, 8 warps (2x4), warp tile 64x32, m16n8k16.
// MODE: 0 = fp32 out to Cout; 1 = fp16 out to Cout;
//       2 = fp16 out TRANSPOSED into g_vt (V GEMM; CTA col tile == one head).
// ---------------------------------------------------------------------------
#define GH_TILE   16384                         // bytes per 128x64-half tile
#define GH_SMEM   (4 * GH_TILE)                 // 64 KB

template <int M, int N, int K, int MODE>
__global__ __launch_bounds__(256, 2) void gemm_f16(const __half* __restrict__ A,
                                                   const __half* __restrict__ Bm,
                                                   void* __restrict__ Cout) {
    extern __shared__ char smem[];
    char* sA = smem;
    char* sB = smem + 2 * GH_TILE;

    const int tid  = threadIdx.x;
    const int lane = tid & 31;
    const int warp = tid >> 5;
    const int warpM = warp >> 2;
    const int warpN = warp & 3;
    const int gid = lane >> 2;
    const int tig = lane & 3;
    const int m0 = blockIdx.y * 128;
    const int n0 = blockIdx.x * 128;

    float c[4][4][4];
#pragma unroll
    for (int i = 0; i < 4; i++)
#pragma unroll
        for (int j = 0; j < 4; j++)
#pragma unroll
            for (int r = 0; r < 4; r++) c[i][j][r] = 0.0f;

    auto issue_tile = [&](int buf, int k0) {
#pragma unroll
        for (int it = 0; it < 4; it++) {
            int flat = it * 256 + tid;
            int row = flat >> 3;
            int ch = flat & 7;
            int sw = (ch ^ (row & 7)) * 16;
            uint32_t da = (uint32_t)__cvta_generic_to_shared(sA + buf * GH_TILE + row * 128 + sw);
            const __half* pa = &A[(size_t)(m0 + row) * K + k0 + ch * 8];
            asm volatile("cp.async.cg.shared.global [%0], [%1], 16;" :: "r"(da), "l"(pa));
            uint32_t db = (uint32_t)__cvta_generic_to_shared(sB + buf * GH_TILE + row * 128 + sw);
            const __half* pb = &Bm[(size_t)(n0 + row) * K + k0 + ch * 8];
            asm volatile("cp.async.cg.shared.global [%0], [%1], 16;" :: "r"(db), "l"(pb));
        }
        asm volatile("cp.async.commit_group;");
    };

    issue_tile(0, 0);
    for (int k0 = 0; k0 < K; k0 += 64) {
        int buf = (k0 >> 6) & 1;
        if (k0 + 64 < K) {
            issue_tile(buf ^ 1, k0 + 64);
            asm volatile("cp.async.wait_group 1;");
        } else {
            asm volatile("cp.async.wait_group 0;");
        }
        __syncthreads();

        const char* cA = sA + buf * GH_TILE;
        const char* cB = sB + buf * GH_TILE;
#pragma unroll
        for (int ks = 0; ks < 4; ks++) {
            uint32_t a[4][4];
#pragma unroll
            for (int i = 0; i < 4; i++) {
                int r = warpM * 64 + i * 16 + gid;
                int rs = r * 128;
                int c0 = ((2 * ks) ^ gid) * 16 + 4 * tig;
                int c1 = ((2 * ks + 1) ^ gid) * 16 + 4 * tig;
                a[i][0] = *(const uint32_t*)(cA + rs + c0);
                a[i][2] = *(const uint32_t*)(cA + rs + c1);
                a[i][1] = *(const uint32_t*)(cA + rs + 1024 + c0);
                a[i][3] = *(const uint32_t*)(cA + rs + 1024 + c1);
            }
            uint32_t b[4][2];
#pragma unroll
            for (int j = 0; j < 4; j++) {
                int n = warpN * 32 + j * 8 + gid;
                int ns = n * 128;
                b[j][0] = *(const uint32_t*)(cB + ns + (((2 * ks) ^ gid) * 16 + 4 * tig));
                b[j][1] = *(const uint32_t*)(cB + ns + (((2 * ks + 1) ^ gid) * 16 + 4 * tig));
            }
#pragma unroll
            for (int i = 0; i < 4; i++)
#pragma unroll
                for (int j = 0; j < 4; j++)
                    mma_f16(c[i][j][0], c[i][j][1], c[i][j][2], c[i][j][3],
                            a[i][0], a[i][1], a[i][2], a[i][3], b[j][0], b[j][1]);
        }
        __syncthreads();
    }

    if (MODE == 2) {
        // Transposed write: stage c-tile as sT[col][row] (stride 136), then
        // coalesced copy into g_vt[b][h][hd=col][s=row]. One head per CTA col.
        __half* sT = (__half*)smem;             // 128 x 136 halves = 34 KB
#pragma unroll
        for (int i = 0; i < 4; i++) {
            int r0l = warpM * 64 + i * 16 + gid;     // local row
#pragma unroll
            for (int j = 0; j < 4; j++) {
                int cl = warpN * 32 + j * 8 + tig * 2;
                sT[(cl)     * 136 + r0l]     = __float2half_rn(c[i][j][0]);
                sT[(cl + 1) * 136 + r0l]     = __float2half_rn(c[i][j][1]);
                sT[(cl)     * 136 + r0l + 8] = __float2half_rn(c[i][j][2]);
                sT[(cl + 1) * 136 + r0l + 8] = __float2half_rn(c[i][j][3]);
            }
        }
        __syncthreads();
        const int b = m0 / SS;
        const int s0 = m0 % SS;
        const int h = n0 / HD;
        __half* vt = g_vt + ((size_t)(b * NH + h)) * HD * SS;
#pragma unroll
        for (int it = 0; it < 8; it++) {
            int flat = it * 256 + tid;          // 0..2047
            int hd = flat >> 4;
            int ch = flat & 15;
            *(uint4*)&vt[(size_t)hd * SS + s0 + ch * 8] =
                *(const uint4*)&sT[hd * 136 + ch * 8];
        }
        return;
    }

#pragma unroll
    for (int i = 0; i < 4; i++) {
        int row0 = m0 + warpM * 64 + i * 16 + gid;
#pragma unroll
        for (int j = 0; j < 4; j++) {
            int col = n0 + warpN * 32 + j * 8 + tig * 2;
            if (MODE == 1) {
                __half* C = (__half*)Cout;
                *(uint32_t*)&C[(size_t)row0 * N + col] = pack_h2(c[i][j][0], c[i][j][1]);
                *(uint32_t*)&C[(size_t)(row0 + 8) * N + col] = pack_h2(c[i][j][2], c[i][j][3]);
            } else {
                float* C = (float*)Cout;
                *(float2*)&C[(size_t)row0 * N + col] = make_float2(c[i][j][0], c[i][j][1]);
                *(float2*)&C[(size_t)(row0 + 8) * N + col] = make_float2(c[i][j][2], c[i][j][3]);
            }
        }
    }
}

// ---------------------------------------------------------------------------
// RoPE on g_q/g_k in place. One thread per (b,s,pair): 1 sincosf, 16 heads.
// position_ids INT32 (JAX x64 disabled).
// ---------------------------------------------------------------------------
__global__ __launch_bounds__(256) void rope_kernel(const int* __restrict__ pos_ids) {
    int idx = blockIdx.x * blockDim.x + threadIdx.x;
    const int total = BB * SS * (HD / 2);
    if (idx >= total) return;
    int i = idx & 63;                 // pair index
    int t = idx >> 6;
    int s = t & (SS - 1);
    int b = t >> 11;

    int p = pos_ids[(size_t)b * SS + s];
    float inv_freq = 1.0f / powf(10000.0f, (float)(2 * i) / (float)HD);
    float ang = (float)p * inv_freq;
    float c, sn;
    sincosf(ang, &sn, &c);

    size_t base = ((size_t)(b * SS + s) * HH) + 2 * i;
#pragma unroll
    for (int h = 0; h < NH; h++) {
        size_t a = base + (size_t)h * HD;
        __half2 q = *(__half2*)&g_q[a];
        float x1 = __low2float(q), x2 = __high2float(q);
        *(__half2*)&g_q[a] = __floats2half2_rn(x1 * c - x2 * sn, x1 * sn + x2 * c);
        __half2 k = *(__half2*)&g_k[a];
        x1 = __low2float(k); x2 = __high2float(k);
        *(__half2*)&g_k[a] = __floats2half2_rn(x1 * c - x2 * sn, x1 * sn + x2 * c);
    }
}

// ---------------------------------------------------------------------------
// FP16 tensor flash attention. BM=BN=64, 4 warps; warp owns 16 q-rows.
// Q resident; K and V^T double-buffered via cp.async (overlap with compute).
// ---------------------------------------------------------------------------
#define FQ_STR 136
#define FP_STR 72
#define FV_STR 72
#define FQ_OFF 0
#define FP_OFF (64 * FQ_STR)
#define FK_OFF (64 * FQ_STR + 64 * FP_STR)
#define FK_SZ  (64 * FQ_STR)
#define FV_OFF (FK_OFF + 2 * FK_SZ)
#define FV_SZ  (128 * FV_STR)
#define FLASH_SMEM_HALVES (FV_OFF + 2 * FV_SZ)

__global__ __launch_bounds__(128) void flash_f16_kernel() {
    extern __shared__ __half sh[];
    __half* sQ = sh + FQ_OFF;
    __half* sP = sh + FP_OFF;

    const int tid = threadIdx.x;
    const int lane = tid & 31;
    const int warp = tid >> 5;
    const int gid = lane >> 2;
    const int tig = lane & 3;
    const int qt = blockIdx.x;
    const int h  = blockIdx.y;
    const int b  = blockIdx.z;
    const int qbase = qt * 64;

    const __half* qp = g_q + ((size_t)b * SS) * HH + (size_t)h * HD;
    const __half* kp = g_k + ((size_t)b * SS) * HH + (size_t)h * HD;
    const __half* vtp = g_vt + ((size_t)(b * NH + h)) * HD * SS;

    const int r0 = warp * 16 + gid;
    const int r1 = r0 + 8;

    // Issue cp.async K+Vt for j-tile jt into buffer buf
    auto issue_kv = [&](int buf, int jt) {
        const int jbase = jt * 64;
        __half* dK = sh + FK_OFF + buf * FK_SZ;
        __half* dV = sh + FV_OFF + buf * FV_SZ;
#pragma unroll
        for (int it = 0; it < 8; it++) {
            int flat = it * 128 + tid;
            int row = flat >> 4;
            int ch = flat & 15;
            uint32_t da = (uint32_t)__cvta_generic_to_shared(&dK[row * FQ_STR + ch * 8]);
            const __half* pk = &kp[(size_t)(jbase + row) * HH + ch * 8];
            asm volatile("cp.async.cg.shared.global [%0], [%1], 16;" :: "r"(da), "l"(pk));
            int vrow = flat >> 3;
            int vch = flat & 7;
            uint32_t dv = (uint32_t)__cvta_generic_to_shared(&dV[vrow * FV_STR + vch * 8]);
            const __half* pv = &vtp[(size_t)vrow * SS + jbase + vch * 8];
            asm volatile("cp.async.cg.shared.global [%0], [%1], 16;" :: "r"(dv), "l"(pv));
        }
        asm volatile("cp.async.commit_group;");
    };

    // Load Q tile (plain)
#pragma unroll
    for (int it = 0; it < 8; it++) {
        int flat = it * 128 + tid;
        int row = flat >> 4;
        int ch = flat & 15;
        *(uint4*)&sQ[row * FQ_STR + ch * 8] =
            *(const uint4*)&qp[(size_t)(qbase + row) * HH + ch * 8];
    }
    issue_kv(0, 0);

    float o[16][4];
#pragma unroll
    for (int j = 0; j < 16; j++)
#pragma unroll
        for (int r = 0; r < 4; r++) o[j][r] = 0.0f;
    float m0 = -CUDART_INF_F, m1 = -CUDART_INF_F;
    float l0 = 0.0f, l1 = 0.0f;

    for (int jt = 0; jt <= qt; jt++) {
        const int jbase = jt * 64;
        const int buf = jt & 1;
        if (jt < qt) {
            issue_kv(buf ^ 1, jt + 1);
            asm volatile("cp.async.wait_group 1;");
        } else {
            asm volatile("cp.async.wait_group 0;");
        }
        __syncthreads();
        const __half* sK = sh + FK_OFF + buf * FK_SZ;
        const __half* sVt = sh + FV_OFF + buf * FV_SZ;

        // ---- scores S = Q K^T ----
        float s[8][4];
#pragma unroll
        for (int j = 0; j < 8; j++)
#pragma unroll
            for (int r = 0; r < 4; r++) s[j][r] = 0.0f;
#pragma unroll
        for (int ks = 0; ks < 8; ks++) {
            const int k0 = ks * 16;
            uint32_t a0 = *(uint32_t*)&sQ[r0 * FQ_STR + k0 + 2 * tig];
            uint32_t a1 = *(uint32_t*)&sQ[r1 * FQ_STR + k0 + 2 * tig];
            uint32_t a2 = *(uint32_t*)&sQ[r0 * FQ_STR + k0 + 8 + 2 * tig];
            uint32_t a3 = *(uint32_t*)&sQ[r1 * FQ_STR + k0 + 8 + 2 * tig];
#pragma unroll
            for (int j = 0; j < 8; j++) {
                int n = j * 8 + gid;
                uint32_t b0 = *(const uint32_t*)&sK[n * FQ_STR + k0 + 2 * tig];
                uint32_t b1 = *(const uint32_t*)&sK[n * FQ_STR + k0 + 8 + 2 * tig];
                mma_f16(s[j][0], s[j][1], s[j][2], s[j][3], a0, a1, a2, a3, b0, b1);
            }
        }

        // ---- scale + causal mask ----
        const bool diag = (jt == qt);
#pragma unroll
        for (int j = 0; j < 8; j++) {
            int col = jbase + j * 8 + tig * 2;
            s[j][0] *= d_scale; s[j][1] *= d_scale;
            s[j][2] *= d_scale; s[j][3] *= d_scale;
            if (diag) {
                int rg0 = qbase + r0, rg1 = qbase + r1;
                if (col     > rg0) s[j][0] = -1e30f;
                if (col + 1 > rg0) s[j][1] = -1e30f;
                if (col     > rg1) s[j][2] = -1e30f;
                if (col + 1 > rg1) s[j][3] = -1e30f;
            }
        }

        // ---- online softmax ----
        float mx0 = -CUDART_INF_F, mx1 = -CUDART_INF_F;
#pragma unroll
        for (int j = 0; j < 8; j++) {
            mx0 = fmaxf(mx0, fmaxf(s[j][0], s[j][1]));
            mx1 = fmaxf(mx1, fmaxf(s[j][2], s[j][3]));
        }
        mx0 = fmaxf(mx0, __shfl_xor_sync(0xffffffffu, mx0, 1));
        mx0 = fmaxf(mx0, __shfl_xor_sync(0xffffffffu, mx0, 2));
        mx1 = fmaxf(mx1, __shfl_xor_sync(0xffffffffu, mx1, 1));
        mx1 = fmaxf(mx1, __shfl_xor_sync(0xffffffffu, mx1, 2));
        float mn0 = fmaxf(m0, mx0), mn1 = fmaxf(m1, mx1);
        float al0 = __expf(m0 - mn0), al1 = __expf(m1 - mn1);
        float rs0 = 0.0f, rs1 = 0.0f;
#pragma unroll
        for (int j = 0; j < 8; j++) {
            s[j][0] = __expf(s[j][0] - mn0);
            s[j][1] = __expf(s[j][1] - mn0);
            s[j][2] = __expf(s[j][2] - mn1);
            s[j][3] = __expf(s[j][3] - mn1);
            rs0 += s[j][0] + s[j][1];
            rs1 += s[j][2] + s[j][3];
        }
        rs0 += __shfl_xor_sync(0xffffffffu, rs0, 1);
        rs0 += __shfl_xor_sync(0xffffffffu, rs0, 2);
        rs1 += __shfl_xor_sync(0xffffffffu, rs1, 1);
        rs1 += __shfl_xor_sync(0xffffffffu, rs1, 2);
        l0 = l0 * al0 + rs0;  m0 = mn0;
        l1 = l1 * al1 + rs1;  m1 = mn1;
#pragma unroll
        for (int j = 0; j < 16; j++) {
            o[j][0] *= al0; o[j][1] *= al0;
            o[j][2] *= al1; o[j][3] *= al1;
        }
#pragma unroll
        for (int j = 0; j < 8; j++) {
            int col = j * 8 + tig * 2;
            *(uint32_t*)&sP[r0 * FP_STR + col] = pack_h2(s[j][0], s[j][1]);
            *(uint32_t*)&sP[r1 * FP_STR + col] = pack_h2(s[j][2], s[j][3]);
        }
        __syncwarp();

        // ---- O += P @ V ----
#pragma unroll
        for (int ks = 0; ks < 4; ks++) {
            const int k0 = ks * 16;
            uint32_t a0 = *(uint32_t*)&sP[r0 * FP_STR + k0 + 2 * tig];
            uint32_t a1 = *(uint32_t*)&sP[r1 * FP_STR + k0 + 2 * tig];
            uint32_t a2 = *(uint32_t*)&sP[r0 * FP_STR + k0 + 8 + 2 * tig];
            uint32_t a3 = *(uint32_t*)&sP[r1 * FP_STR + k0 + 8 + 2 * tig];
#pragma unroll
            for (int j = 0; j < 16; j++) {
                int n = j * 8 + gid;
                uint32_t b0 = *(const uint32_t*)&sVt[n * FV_STR + k0 + 2 * tig];
                uint32_t b1 = *(const uint32_t*)&sVt[n * FV_STR + k0 + 8 + 2 * tig];
                mma_f16(o[j][0], o[j][1], o[j][2], o[j][3], a0, a1, a2, a3, b0, b1);
            }
        }
        __syncthreads();     // all warps done with this buf before reuse
    }

    // ---- epilogue ----
    __half* cp = g_ctx + ((size_t)b * SS) * HH + (size_t)h * HD;
    float inv0 = 1.0f / l0, inv1 = 1.0f / l1;
    size_t grow0 = (size_t)(qbase + r0) * HH;
    size_t grow1 = (size_t)(qbase + r1) * HH;
#pragma unroll
    for (int j = 0; j < 16; j++) {
        int col = j * 8 + tig * 2;
        *(uint32_t*)&cp[grow0 + col] = pack_h2(o[j][0] * inv0, o[j][1] * inv0);
        *(uint32_t*)&cp[grow1 + col] = pack_h2(o[j][2] * inv1, o[j][3] * inv1);
    }
}

// ---------------------------------------------------------------------------
extern "C" void kernel_launch(void* const* d_in, const int* in_sizes, int n_in,
                              void* d_out, int out_size) {
    const float* hidden = (const float*)d_in[0];
    const float* Wq = (const float*)d_in[1];
    const float* Wk = (const float*)d_in[2];
    const float* Wv = (const float*)d_in[3];
    const float* Wd = (const float*)d_in[4];
    const int* pos = (const int*)d_in[6];
    float* out = (float*)d_out;

    __half *qptr, *kptr, *cptr, *hptr, *wqp, *wkp, *wvp, *wdp;
    cudaGetSymbolAddress((void**)&qptr, g_q);
    cudaGetSymbolAddress((void**)&kptr, g_k);
    cudaGetSymbolAddress((void**)&cptr, g_ctx);
    cudaGetSymbolAddress((void**)&hptr, g_hid);
    cudaGetSymbolAddress((void**)&wqp, g_wq);
    cudaGetSymbolAddress((void**)&wkp, g_wk);
    cudaGetSymbolAddress((void**)&wvp, g_wv);
    cudaGetSymbolAddress((void**)&wdp, g_wd);

    cudaFuncSetAttribute(gemm_f16<MTOT, HH, HH, 0>,
                         cudaFuncAttributeMaxDynamicSharedMemorySize, GH_SMEM);
    cudaFuncSetAttribute(gemm_f16<MTOT, HH, HH, 1>,
                         cudaFuncAttributeMaxDynamicSharedMemorySize, GH_SMEM);
    cudaFuncSetAttribute(gemm_f16<MTOT, HH, HH, 2>,
                         cudaFuncAttributeMaxDynamicSharedMemorySize, GH_SMEM);
    cudaFuncSetAttribute(flash_f16_kernel,
                         cudaFuncAttributeMaxDynamicSharedMemorySize,
                         FLASH_SMEM_HALVES * (int)sizeof(__half));

    // One conversion launch: hidden (2 slices) + 4 weights
    int nw4 = HH * HH / 4;
    dim3 conv_grid((nw4 + 255) / 256, 1, 6);
    conv_all_kernel<<<conv_grid, 256>>>((const float4*)hidden, (const float4*)Wq,
                                        (const float4*)Wk, (const float4*)Wv,
                                        (const float4*)Wd, nw4);

    dim3 gemm_grid(HH / 128, MTOT / 128);   // (16, 32)
    gemm_f16<MTOT, HH, HH, 1><<<gemm_grid, 256, GH_SMEM>>>(hptr, wqp, qptr);
    gemm_f16<MTOT, HH, HH, 1><<<gemm_grid, 256, GH_SMEM>>>(hptr, wkp, kptr);
    gemm_f16<MTOT, HH, HH, 2><<<gemm_grid, 256, GH_SMEM>>>(hptr, wvp, nullptr);

    int rope_total = BB * SS * (HD / 2);
    rope_kernel<<<(rope_total + 255) / 256, 256>>>(pos);

    dim3 flash_grid(SS / 64, NH, BB);
    flash_f16_kernel<<<flash_grid, 128, FLASH_SMEM_HALVES * sizeof(__half)>>>();

    gemm_f16<MTOT, HH, HH, 0><<<gemm_grid, 256, GH_SMEM>>>(cptr, wdp, out);
}

// round 11
// speedup vs baseline: 8.9704x; 1.0820x over previous
#include <cuda_runtime.h>
#include <cuda_fp16.h>
#include <math.h>
#include <math_constants.h>
#include <stdint.h>

#define BB   2
#define SS   2048
#define HH   2048
#define NH   16
#define HD   128
#define MTOT (BB * SS)
static __device__ __constant__ float d_scale = 0.08838834764831843f; // 1/sqrt(128)

// Scratch (allocation-free: __device__ globals) — all fp16 intermediates
__device__ __half g_q[(size_t)BB * SS * HH];
__device__ __half g_k[(size_t)BB * SS * HH];
__device__ __half g_vt[(size_t)BB * NH * HD * SS];   // [b][h][hd][s]
__device__ __half g_ctx[(size_t)BB * SS * HH];
__device__ __half g_hid[(size_t)MTOT * HH];
__device__ __half g_wq[(size_t)HH * HH];
__device__ __half g_wk[(size_t)HH * HH];
__device__ __half g_wv[(size_t)HH * HH];
__device__ __half g_wd[(size_t)HH * HH];

__device__ __forceinline__ void mma_f16(float& c0, float& c1, float& c2, float& c3,
                                        uint32_t a0, uint32_t a1, uint32_t a2, uint32_t a3,
                                        uint32_t b0, uint32_t b1) {
    asm volatile(
        "mma.sync.aligned.m16n8k16.row.col.f32.f16.f16.f32 "
        "{%0,%1,%2,%3}, {%4,%5,%6,%7}, {%8,%9}, {%0,%1,%2,%3};"
        : "+f"(c0), "+f"(c1), "+f"(c2), "+f"(c3)
        : "r"(a0), "r"(a1), "r"(a2), "r"(a3), "r"(b0), "r"(b1));
}

__device__ __forceinline__ void ldsm_x4(uint32_t& r0, uint32_t& r1,
                                        uint32_t& r2, uint32_t& r3, uint32_t addr) {
    asm volatile("ldmatrix.sync.aligned.m8n8.x4.shared.b16 {%0,%1,%2,%3}, [%4];"
                 : "=r"(r0), "=r"(r1), "=r"(r2), "=r"(r3) : "r"(addr));
}

__device__ __forceinline__ uint32_t pack_h2(float lo, float hi) {
    __half2 h = __floats2half2_rn(lo, hi);
    return *(uint32_t*)&h;
}

// ---------------------------------------------------------------------------
// Combined fp32 -> fp16 conversion: z-slice 0,1 = hidden halves, 2..5 = W*.
// ---------------------------------------------------------------------------
__global__ __launch_bounds__(256) void conv_all_kernel(
        const float4* __restrict__ hid, const float4* __restrict__ wq,
        const float4* __restrict__ wk, const float4* __restrict__ wv,
        const float4* __restrict__ wd, int n4) {
    int i = blockIdx.x * blockDim.x + threadIdx.x;
    if (i >= n4) return;
    int z = blockIdx.z;
    const float4* src;
    uint2* dst;
    switch (z) {
        case 0: src = hid;       dst = (uint2*)g_hid;        break;
        case 1: src = hid + n4;  dst = (uint2*)g_hid + n4;   break;
        case 2: src = wq;        dst = (uint2*)g_wq;         break;
        case 3: src = wk;        dst = (uint2*)g_wk;         break;
        case 4: src = wv;        dst = (uint2*)g_wv;         break;
        default: src = wd;       dst = (uint2*)g_wd;         break;
    }
    float4 v = src[i];
    uint2 o;
    o.x = pack_h2(v.x, v.y);
    o.y = pack_h2(v.z, v.w);
    dst[i] = o;
}

// ---------------------------------------------------------------------------
// FP16 tensor GEMM (M=4096, N=2048, K=2048 fixed): C = A * B^T.
// Block 128x128x64, 8 warps (2x4), warp tile 64x32, m16n8k16, cp.async
// double buffer, XOR-swizzled smem, ldmatrix fragment loads.
// MODE 0: fp32 out to Cout (Wd GEMM).
// MODE 3: fused QKV — blockIdx.z selects weight/epilogue:
//         z=0 -> g_q (fp16), z=1 -> g_k (fp16), z=2 -> g_vt (transposed).
// ---------------------------------------------------------------------------
#define GH_TILE   16384
#define GH_SMEM   (4 * GH_TILE)                 // 64 KB
#define GM MTOT
#define GN HH
#define GK HH

template <int MODE>
__global__ __launch_bounds__(256, 2) void gemm_f16(const __half* __restrict__ A,
                                                   const __half* __restrict__ Bm_,
                                                   void* __restrict__ Cout) {
    extern __shared__ char smem[];
    char* sA = smem;
    char* sB = smem + 2 * GH_TILE;
    const uint32_t sbase = (uint32_t)__cvta_generic_to_shared(smem);

    const int z = (MODE == 3) ? blockIdx.z : 0;
    const __half* Bm = (MODE == 3) ? ((z == 0) ? g_wq : (z == 1) ? g_wk : g_wv) : Bm_;

    const int tid  = threadIdx.x;
    const int lane = tid & 31;
    const int warp = tid >> 5;
    const int warpM = warp >> 2;
    const int warpN = warp & 3;
    const int gid = lane >> 2;
    const int tig = lane & 3;
    const int m0 = blockIdx.y * 128;
    const int n0 = blockIdx.x * 128;

    // ldmatrix per-lane geometry: matrix idx m=lane>>3; row-in-16 & chunk-select
    const int lm   = lane >> 3;
    const int rsub = (lm & 1) * 8 + (lane & 7);
    const int csel = lm >> 1;                     // 0 or 1 -> chunk 2ks / 2ks+1
    // A row bases (4 i-tiles) and B row bases (2 jj pairs), plus their bank keys
    int rowA[4], qa[4];
#pragma unroll
    for (int i = 0; i < 4; i++) {
        rowA[i] = warpM * 64 + i * 16 + rsub;
        qa[i] = rowA[i] & 7;
    }
    int rowB[2], qb[2];
#pragma unroll
    for (int jj = 0; jj < 2; jj++) {
        rowB[jj] = warpN * 32 + jj * 16 + rsub;
        qb[jj] = rowB[jj] & 7;
    }

    float c[4][4][4];
#pragma unroll
    for (int i = 0; i < 4; i++)
#pragma unroll
        for (int j = 0; j < 4; j++)
#pragma unroll
            for (int r = 0; r < 4; r++) c[i][j][r] = 0.0f;

    auto issue_tile = [&](int buf, int k0) {
#pragma unroll
        for (int it = 0; it < 4; it++) {
            int flat = it * 256 + tid;
            int row = flat >> 3;
            int ch = flat & 7;
            int sw = (ch ^ (row & 7)) * 16;
            uint32_t da = (uint32_t)__cvta_generic_to_shared(sA + buf * GH_TILE + row * 128 + sw);
            const __half* pa = &A[(size_t)(m0 + row) * GK + k0 + ch * 8];
            asm volatile("cp.async.cg.shared.global [%0], [%1], 16;" :: "r"(da), "l"(pa));
            uint32_t db = (uint32_t)__cvta_generic_to_shared(sB + buf * GH_TILE + row * 128 + sw);
            const __half* pb = &Bm[(size_t)(n0 + row) * GK + k0 + ch * 8];
            asm volatile("cp.async.cg.shared.global [%0], [%1], 16;" :: "r"(db), "l"(pb));
        }
        asm volatile("cp.async.commit_group;");
    };

    issue_tile(0, 0);
    for (int k0 = 0; k0 < GK; k0 += 64) {
        int buf = (k0 >> 6) & 1;
        if (k0 + 64 < GK) {
            issue_tile(buf ^ 1, k0 + 64);
            asm volatile("cp.async.wait_group 1;");
        } else {
            asm volatile("cp.async.wait_group 0;");
        }
        __syncthreads();

        const uint32_t aBuf = sbase + buf * GH_TILE;
        const uint32_t bBuf = sbase + 2 * GH_TILE + buf * GH_TILE;
#pragma unroll
        for (int ks = 0; ks < 4; ks++) {
            const int cbase = 2 * ks + csel;
            uint32_t a[4][4];
#pragma unroll
            for (int i = 0; i < 4; i++)
                ldsm_x4(a[i][0], a[i][1], a[i][2], a[i][3],
                        aBuf + rowA[i] * 128 + ((cbase ^ qa[i]) << 4));
            uint32_t b[4][2];
            ldsm_x4(b[0][0], b[1][0], b[0][1], b[1][1],
                    bBuf + rowB[0] * 128 + ((cbase ^ qb[0]) << 4));
            ldsm_x4(b[2][0], b[3][0], b[2][1], b[3][1],
                    bBuf + rowB[1] * 128 + ((cbase ^ qb[1]) << 4));
#pragma unroll
            for (int i = 0; i < 4; i++)
#pragma unroll
                for (int j = 0; j < 4; j++)
                    mma_f16(c[i][j][0], c[i][j][1], c[i][j][2], c[i][j][3],
                            a[i][0], a[i][1], a[i][2], a[i][3], b[j][0], b[j][1]);
        }
        __syncthreads();
    }

    if (MODE == 3 && z == 2) {
        // Transposed write to g_vt[b][h][hd][s] via smem staging.
        __half* sT = (__half*)smem;             // 128 x 136 halves
#pragma unroll
        for (int i = 0; i < 4; i++) {
            int r0l = warpM * 64 + i * 16 + gid;
#pragma unroll
            for (int j = 0; j < 4; j++) {
                int cl = warpN * 32 + j * 8 + tig * 2;
                sT[(cl)     * 136 + r0l]     = __float2half_rn(c[i][j][0]);
                sT[(cl + 1) * 136 + r0l]     = __float2half_rn(c[i][j][1]);
                sT[(cl)     * 136 + r0l + 8] = __float2half_rn(c[i][j][2]);
                sT[(cl + 1) * 136 + r0l + 8] = __float2half_rn(c[i][j][3]);
            }
        }
        __syncthreads();
        const int b = m0 / SS;
        const int s0 = m0 % SS;
        const int h = n0 / HD;
        __half* vt = g_vt + ((size_t)(b * NH + h)) * HD * SS;
#pragma unroll
        for (int it = 0; it < 8; it++) {
            int flat = it * 256 + tid;
            int hd = flat >> 4;
            int ch = flat & 15;
            *(uint4*)&vt[(size_t)hd * SS + s0 + ch * 8] =
                *(const uint4*)&sT[hd * 136 + ch * 8];
        }
        return;
    }

#pragma unroll
    for (int i = 0; i < 4; i++) {
        int row0 = m0 + warpM * 64 + i * 16 + gid;
#pragma unroll
        for (int j = 0; j < 4; j++) {
            int col = n0 + warpN * 32 + j * 8 + tig * 2;
            if (MODE == 3) {
                __half* C = (z == 0) ? g_q : g_k;
                *(uint32_t*)&C[(size_t)row0 * GN + col] = pack_h2(c[i][j][0], c[i][j][1]);
                *(uint32_t*)&C[(size_t)(row0 + 8) * GN + col] = pack_h2(c[i][j][2], c[i][j][3]);
            } else {
                float* C = (float*)Cout;
                *(float2*)&C[(size_t)row0 * GN + col] = make_float2(c[i][j][0], c[i][j][1]);
                *(float2*)&C[(size_t)(row0 + 8) * GN + col] = make_float2(c[i][j][2], c[i][j][3]);
            }
        }
    }
}

// ---------------------------------------------------------------------------
// RoPE on g_q/g_k in place. One thread per (b,s,pair): 1 sincosf, 16 heads.
// position_ids INT32 (JAX x64 disabled).
// ---------------------------------------------------------------------------
__global__ __launch_bounds__(256) void rope_kernel(const int* __restrict__ pos_ids) {
    int idx = blockIdx.x * blockDim.x + threadIdx.x;
    const int total = BB * SS * (HD / 2);
    if (idx >= total) return;
    int i = idx & 63;
    int t = idx >> 6;
    int s = t & (SS - 1);
    int b = t >> 11;

    int p = pos_ids[(size_t)b * SS + s];
    float inv_freq = 1.0f / powf(10000.0f, (float)(2 * i) / (float)HD);
    float ang = (float)p * inv_freq;
    float c, sn;
    sincosf(ang, &sn, &c);

    size_t base = ((size_t)(b * SS + s) * HH) + 2 * i;
#pragma unroll
    for (int h = 0; h < NH; h++) {
        size_t a = base + (size_t)h * HD;
        __half2 q = *(__half2*)&g_q[a];
        float x1 = __low2float(q), x2 = __high2float(q);
        *(__half2*)&g_q[a] = __floats2half2_rn(x1 * c - x2 * sn, x1 * sn + x2 * c);
        __half2 k = *(__half2*)&g_k[a];
        x1 = __low2float(k); x2 = __high2float(k);
        *(__half2*)&g_k[a] = __floats2half2_rn(x1 * c - x2 * sn, x1 * sn + x2 * c);
    }
}

// ---------------------------------------------------------------------------
// FP16 tensor flash attention. BM=BN=64, 4 warps; warp owns 16 q-rows.
// Q resident; K and V^T double-buffered via cp.async.
// ---------------------------------------------------------------------------
#define FQ_STR 136
#define FP_STR 72
#define FV_STR 72
#define FQ_OFF 0
#define FP_OFF (64 * FQ_STR)
#define FK_OFF (64 * FQ_STR + 64 * FP_STR)
#define FK_SZ  (64 * FQ_STR)
#define FV_OFF (FK_OFF + 2 * FK_SZ)
#define FV_SZ  (128 * FV_STR)
#define FLASH_SMEM_HALVES (FV_OFF + 2 * FV_SZ)

__global__ __launch_bounds__(128) void flash_f16_kernel() {
    extern __shared__ __half sh[];
    __half* sQ = sh + FQ_OFF;
    __half* sP = sh + FP_OFF;

    const int tid = threadIdx.x;
    const int lane = tid & 31;
    const int warp = tid >> 5;
    const int gid = lane >> 2;
    const int tig = lane & 3;
    const int qt = blockIdx.x;
    const int h  = blockIdx.y;
    const int b  = blockIdx.z;
    const int qbase = qt * 64;

    const __half* qp = g_q + ((size_t)b * SS) * HH + (size_t)h * HD;
    const __half* kp = g_k + ((size_t)b * SS) * HH + (size_t)h * HD;
    const __half* vtp = g_vt + ((size_t)(b * NH + h)) * HD * SS;

    const int r0 = warp * 16 + gid;
    const int r1 = r0 + 8;

    auto issue_kv = [&](int buf, int jt) {
        const int jbase = jt * 64;
        __half* dK = sh + FK_OFF + buf * FK_SZ;
        __half* dV = sh + FV_OFF + buf * FV_SZ;
#pragma unroll
        for (int it = 0; it < 8; it++) {
            int flat = it * 128 + tid;
            int row = flat >> 4;
            int ch = flat & 15;
            uint32_t da = (uint32_t)__cvta_generic_to_shared(&dK[row * FQ_STR + ch * 8]);
            const __half* pk = &kp[(size_t)(jbase + row) * HH + ch * 8];
            asm volatile("cp.async.cg.shared.global [%0], [%1], 16;" :: "r"(da), "l"(pk));
            int vrow = flat >> 3;
            int vch = flat & 7;
            uint32_t dv = (uint32_t)__cvta_generic_to_shared(&dV[vrow * FV_STR + vch * 8]);
            const __half* pv = &vtp[(size_t)vrow * SS + jbase + vch * 8];
            asm volatile("cp.async.cg.shared.global [%0], [%1], 16;" :: "r"(dv), "l"(pv));
        }
        asm volatile("cp.async.commit_group;");
    };

#pragma unroll
    for (int it = 0; it < 8; it++) {
        int flat = it * 128 + tid;
        int row = flat >> 4;
        int ch = flat & 15;
        *(uint4*)&sQ[row * FQ_STR + ch * 8] =
            *(const uint4*)&qp[(size_t)(qbase + row) * HH + ch * 8];
    }
    issue_kv(0, 0);

    float o[16][4];
#pragma unroll
    for (int j = 0; j < 16; j++)
#pragma unroll
        for (int r = 0; r < 4; r++) o[j][r] = 0.0f;
    float m0 = -CUDART_INF_F, m1 = -CUDART_INF_F;
    float l0 = 0.0f, l1 = 0.0f;

    for (int jt = 0; jt <= qt; jt++) {
        const int jbase = jt * 64;
        const int buf = jt & 1;
        if (jt < qt) {
            issue_kv(buf ^ 1, jt + 1);
            asm volatile("cp.async.wait_group 1;");
        } else {
            asm volatile("cp.async.wait_group 0;");
        }
        __syncthreads();
        const __half* sK = sh + FK_OFF + buf * FK_SZ;
        const __half* sVt = sh + FV_OFF + buf * FV_SZ;

        float s[8][4];
#pragma unroll
        for (int j = 0; j < 8; j++)
#pragma unroll
            for (int r = 0; r < 4; r++) s[j][r] = 0.0f;
#pragma unroll
        for (int ks = 0; ks < 8; ks++) {
            const int k0 = ks * 16;
            uint32_t a0 = *(uint32_t*)&sQ[r0 * FQ_STR + k0 + 2 * tig];
            uint32_t a1 = *(uint32_t*)&sQ[r1 * FQ_STR + k0 + 2 * tig];
            uint32_t a2 = *(uint32_t*)&sQ[r0 * FQ_STR + k0 + 8 + 2 * tig];
            uint32_t a3 = *(uint32_t*)&sQ[r1 * FQ_STR + k0 + 8 + 2 * tig];
#pragma unroll
            for (int j = 0; j < 8; j++) {
                int n = j * 8 + gid;
                uint32_t b0 = *(const uint32_t*)&sK[n * FQ_STR + k0 + 2 * tig];
                uint32_t b1 = *(const uint32_t*)&sK[n * FQ_STR + k0 + 8 + 2 * tig];
                mma_f16(s[j][0], s[j][1], s[j][2], s[j][3], a0, a1, a2, a3, b0, b1);
            }
        }

        const bool diag = (jt == qt);
#pragma unroll
        for (int j = 0; j < 8; j++) {
            int col = jbase + j * 8 + tig * 2;
            s[j][0] *= d_scale; s[j][1] *= d_scale;
            s[j][2] *= d_scale; s[j][3] *= d_scale;
            if (diag) {
                int rg0 = qbase + r0, rg1 = qbase + r1;
                if (col     > rg0) s[j][0] = -1e30f;
                if (col + 1 > rg0) s[j][1] = -1e30f;
                if (col     > rg1) s[j][2] = -1e30f;
                if (col + 1 > rg1) s[j][3] = -1e30f;
            }
        }

        float mx0 = -CUDART_INF_F, mx1 = -CUDART_INF_F;
#pragma unroll
        for (int j = 0; j < 8; j++) {
            mx0 = fmaxf(mx0, fmaxf(s[j][0], s[j][1]));
            mx1 = fmaxf(mx1, fmaxf(s[j][2], s[j][3]));
        }
        mx0 = fmaxf(mx0, __shfl_xor_sync(0xffffffffu, mx0, 1));
        mx0 = fmaxf(mx0, __shfl_xor_sync(0xffffffffu, mx0, 2));
        mx1 = fmaxf(mx1, __shfl_xor_sync(0xffffffffu, mx1, 1));
        mx1 = fmaxf(mx1, __shfl_xor_sync(0xffffffffu, mx1, 2));
        float mn0 = fmaxf(m0, mx0), mn1 = fmaxf(m1, mx1);
        float al0 = __expf(m0 - mn0), al1 = __expf(m1 - mn1);
        float rs0 = 0.0f, rs1 = 0.0f;
#pragma unroll
        for (int j = 0; j < 8; j++) {
            s[j][0] = __expf(s[j][0] - mn0);
            s[j][1] = __expf(s[j][1] - mn0);
            s[j][2] = __expf(s[j][2] - mn1);
            s[j][3] = __expf(s[j][3] - mn1);
            rs0 += s[j][0] + s[j][1];
            rs1 += s[j][2] + s[j][3];
        }
        rs0 += __shfl_xor_sync(0xffffffffu, rs0, 1);
        rs0 += __shfl_xor_sync(0xffffffffu, rs0, 2);
        rs1 += __shfl_xor_sync(0xffffffffu, rs1, 1);
        rs1 += __shfl_xor_sync(0xffffffffu, rs1, 2);
        l0 = l0 * al0 + rs0;  m0 = mn0;
        l1 = l1 * al1 + rs1;  m1 = mn1;
#pragma unroll
        for (int j = 0; j < 16; j++) {
            o[j][0] *= al0; o[j][1] *= al0;
            o[j][2] *= al1; o[j][3] *= al1;
        }
#pragma unroll
        for (int j = 0; j < 8; j++) {
            int col = j * 8 + tig * 2;
            *(uint32_t*)&sP[r0 * FP_STR + col] = pack_h2(s[j][0], s[j][1]);
            *(uint32_t*)&sP[r1 * FP_STR + col] = pack_h2(s[j][2], s[j][3]);
        }
        __syncwarp();

#pragma unroll
        for (int ks = 0; ks < 4; ks++) {
            const int k0 = ks * 16;
            uint32_t a0 = *(uint32_t*)&sP[r0 * FP_STR + k0 + 2 * tig];
            uint32_t a1 = *(uint32_t*)&sP[r1 * FP_STR + k0 + 2 * tig];
            uint32_t a2 = *(uint32_t*)&sP[r0 * FP_STR + k0 + 8 + 2 * tig];
            uint32_t a3 = *(uint32_t*)&sP[r1 * FP_STR + k0 + 8 + 2 * tig];
#pragma unroll
            for (int j = 0; j < 16; j++) {
                int n = j * 8 + gid;
                uint32_t b0 = *(const uint32_t*)&sVt[n * FV_STR + k0 + 2 * tig];
                uint32_t b1 = *(const uint32_t*)&sVt[n * FV_STR + k0 + 8 + 2 * tig];
                mma_f16(o[j][0], o[j][1], o[j][2], o[j][3], a0, a1, a2, a3, b0, b1);
            }
        }
        __syncthreads();
    }

    __half* cp = g_ctx + ((size_t)b * SS) * HH + (size_t)h * HD;
    float inv0 = 1.0f / l0, inv1 = 1.0f / l1;
    size_t grow0 = (size_t)(qbase + r0) * HH;
    size_t grow1 = (size_t)(qbase + r1) * HH;
#pragma unroll
    for (int j = 0; j < 16; j++) {
        int col = j * 8 + tig * 2;
        *(uint32_t*)&cp[grow0 + col] = pack_h2(o[j][0] * inv0, o[j][1] * inv0);
        *(uint32_t*)&cp[grow1 + col] = pack_h2(o[j][2] * inv1, o[j][3] * inv1);
    }
}

// ---------------------------------------------------------------------------
extern "C" void kernel_launch(void* const* d_in, const int* in_sizes, int n_in,
                              void* d_out, int out_size) {
    const float* hidden = (const float*)d_in[0];
    const float* Wq = (const float*)d_in[1];
    const float* Wk = (const float*)d_in[2];
    const float* Wv = (const float*)d_in[3];
    const float* Wd = (const float*)d_in[4];
    const int* pos = (const int*)d_in[6];
    float* out = (float*)d_out;

    __half *cptr, *hptr, *wdp;
    cudaGetSymbolAddress((void**)&cptr, g_ctx);
    cudaGetSymbolAddress((void**)&hptr, g_hid);
    cudaGetSymbolAddress((void**)&wdp, g_wd);

    cudaFuncSetAttribute(gemm_f16<0>,
                         cudaFuncAttributeMaxDynamicSharedMemorySize, GH_SMEM);
    cudaFuncSetAttribute(gemm_f16<3>,
                         cudaFuncAttributeMaxDynamicSharedMemorySize, GH_SMEM);
    cudaFuncSetAttribute(flash_f16_kernel,
                         cudaFuncAttributeMaxDynamicSharedMemorySize,
                         FLASH_SMEM_HALVES * (int)sizeof(__half));

    // One conversion launch: hidden (2 slices) + 4 weights
    int nw4 = HH * HH / 4;
    dim3 conv_grid((nw4 + 255) / 256, 1, 6);
    conv_all_kernel<<<conv_grid, 256>>>((const float4*)hidden, (const float4*)Wq,
                                        (const float4*)Wk, (const float4*)Wv,
                                        (const float4*)Wd, nw4);

    // Fused QKV GEMM (z selects weight + epilogue)
    dim3 qkv_grid(HH / 128, MTOT / 128, 3);
    gemm_f16<3><<<qkv_grid, 256, GH_SMEM>>>(hptr, nullptr, nullptr);

    int rope_total = BB * SS * (HD / 2);
    rope_kernel<<<(rope_total + 255) / 256, 256>>>(pos);

    dim3 flash_grid(SS / 64, NH, BB);
    flash_f16_kernel<<<flash_grid, 128, FLASH_SMEM_HALVES * sizeof(__half)>>>();

    dim3 gemm_grid(HH / 128, MTOT / 128);
    gemm_f16<0><<<gemm_grid, 256, GH_SMEM>>>(cptr, wdp, out);
}

// round 12
// speedup vs baseline: 9.0260x; 1.0062x over previous
#include <cuda_runtime.h>
#include <cuda_fp16.h>
#include <math.h>
#include <math_constants.h>
#include <stdint.h>

#define BB   2
#define SS   2048
#define HH   2048
#define NH   16
#define HD   128
#define MTOT (BB * SS)
static __device__ __constant__ float d_scale = 0.08838834764831843f; // 1/sqrt(128)

// Scratch (allocation-free: __device__ globals) — all fp16 intermediates
__device__ __half g_q[(size_t)BB * SS * HH];
__device__ __half g_k[(size_t)BB * SS * HH];
__device__ __half g_vt[(size_t)BB * NH * HD * SS];   // [b][h][hd][s]
__device__ __half g_ctx[(size_t)BB * SS * HH];
__device__ __half g_hid[(size_t)MTOT * HH];
__device__ __half g_wq[(size_t)HH * HH];
__device__ __half g_wk[(size_t)HH * HH];
__device__ __half g_wv[(size_t)HH * HH];
__device__ __half g_wd[(size_t)HH * HH];

__device__ __forceinline__ void mma_f16(float& c0, float& c1, float& c2, float& c3,
                                        uint32_t a0, uint32_t a1, uint32_t a2, uint32_t a3,
                                        uint32_t b0, uint32_t b1) {
    asm volatile(
        "mma.sync.aligned.m16n8k16.row.col.f32.f16.f16.f32 "
        "{%0,%1,%2,%3}, {%4,%5,%6,%7}, {%8,%9}, {%0,%1,%2,%3};"
        : "+f"(c0), "+f"(c1), "+f"(c2), "+f"(c3)
        : "r"(a0), "r"(a1), "r"(a2), "r"(a3), "r"(b0), "r"(b1));
}

__device__ __forceinline__ void ldsm_x4(uint32_t& r0, uint32_t& r1,
                                        uint32_t& r2, uint32_t& r3, uint32_t addr) {
    asm volatile("ldmatrix.sync.aligned.m8n8.x4.shared.b16 {%0,%1,%2,%3}, [%4];"
                 : "=r"(r0), "=r"(r1), "=r"(r2), "=r"(r3) : "r"(addr));
}

__device__ __forceinline__ uint32_t pack_h2(float lo, float hi) {
    __half2 h = __floats2half2_rn(lo, hi);
    return *(uint32_t*)&h;
}

// ---------------------------------------------------------------------------
// Combined fp32 -> fp16 conversion: z-slice 0,1 = hidden halves, 2..5 = W*.
// ---------------------------------------------------------------------------
__global__ __launch_bounds__(256) void conv_all_kernel(
        const float4* __restrict__ hid, const float4* __restrict__ wq,
        const float4* __restrict__ wk, const float4* __restrict__ wv,
        const float4* __restrict__ wd, int n4) {
    int i = blockIdx.x * blockDim.x + threadIdx.x;
    if (i >= n4) return;
    int z = blockIdx.z;
    const float4* src;
    uint2* dst;
    switch (z) {
        case 0: src = hid;       dst = (uint2*)g_hid;        break;
        case 1: src = hid + n4;  dst = (uint2*)g_hid + n4;   break;
        case 2: src = wq;        dst = (uint2*)g_wq;         break;
        case 3: src = wk;        dst = (uint2*)g_wk;         break;
        case 4: src = wv;        dst = (uint2*)g_wv;         break;
        default: src = wd;       dst = (uint2*)g_wd;         break;
    }
    float4 v = src[i];
    uint2 o;
    o.x = pack_h2(v.x, v.y);
    o.y = pack_h2(v.z, v.w);
    dst[i] = o;
}

// ---------------------------------------------------------------------------
// FP16 tensor GEMM (M=4096, N=2048, K=2048): C = A * B^T. ldmatrix frags.
// MODE 0: fp32 out (Wd). MODE 3: fused QKV via blockIdx.z (z=2 -> g_vt^T).
// ---------------------------------------------------------------------------
#define GH_TILE   16384
#define GH_SMEM   (4 * GH_TILE)                 // 64 KB
#define GN HH
#define GK HH

template <int MODE>
__global__ __launch_bounds__(256, 2) void gemm_f16(const __half* __restrict__ A,
                                                   const __half* __restrict__ Bm_,
                                                   void* __restrict__ Cout) {
    extern __shared__ char smem[];
    char* sA = smem;
    char* sB = smem + 2 * GH_TILE;
    const uint32_t sbase = (uint32_t)__cvta_generic_to_shared(smem);

    const int z = (MODE == 3) ? blockIdx.z : 0;
    const __half* Bm = (MODE == 3) ? ((z == 0) ? g_wq : (z == 1) ? g_wk : g_wv) : Bm_;

    const int tid  = threadIdx.x;
    const int lane = tid & 31;
    const int warp = tid >> 5;
    const int warpM = warp >> 2;
    const int warpN = warp & 3;
    const int gid = lane >> 2;
    const int tig = lane & 3;
    const int m0 = blockIdx.y * 128;
    const int n0 = blockIdx.x * 128;

    const int lm   = lane >> 3;
    const int rsub = (lm & 1) * 8 + (lane & 7);
    const int csel = lm >> 1;
    int rowA[4], qa[4];
#pragma unroll
    for (int i = 0; i < 4; i++) {
        rowA[i] = warpM * 64 + i * 16 + rsub;
        qa[i] = rowA[i] & 7;
    }
    int rowB[2], qb[2];
#pragma unroll
    for (int jj = 0; jj < 2; jj++) {
        rowB[jj] = warpN * 32 + jj * 16 + rsub;
        qb[jj] = rowB[jj] & 7;
    }

    float c[4][4][4];
#pragma unroll
    for (int i = 0; i < 4; i++)
#pragma unroll
        for (int j = 0; j < 4; j++)
#pragma unroll
            for (int r = 0; r < 4; r++) c[i][j][r] = 0.0f;

    auto issue_tile = [&](int buf, int k0) {
#pragma unroll
        for (int it = 0; it < 4; it++) {
            int flat = it * 256 + tid;
            int row = flat >> 3;
            int ch = flat & 7;
            int sw = (ch ^ (row & 7)) * 16;
            uint32_t da = (uint32_t)__cvta_generic_to_shared(sA + buf * GH_TILE + row * 128 + sw);
            const __half* pa = &A[(size_t)(m0 + row) * GK + k0 + ch * 8];
            asm volatile("cp.async.cg.shared.global [%0], [%1], 16;" :: "r"(da), "l"(pa));
            uint32_t db = (uint32_t)__cvta_generic_to_shared(sB + buf * GH_TILE + row * 128 + sw);
            const __half* pb = &Bm[(size_t)(n0 + row) * GK + k0 + ch * 8];
            asm volatile("cp.async.cg.shared.global [%0], [%1], 16;" :: "r"(db), "l"(pb));
        }
        asm volatile("cp.async.commit_group;");
    };

    issue_tile(0, 0);
    for (int k0 = 0; k0 < GK; k0 += 64) {
        int buf = (k0 >> 6) & 1;
        if (k0 + 64 < GK) {
            issue_tile(buf ^ 1, k0 + 64);
            asm volatile("cp.async.wait_group 1;");
        } else {
            asm volatile("cp.async.wait_group 0;");
        }
        __syncthreads();

        const uint32_t aBuf = sbase + buf * GH_TILE;
        const uint32_t bBuf = sbase + 2 * GH_TILE + buf * GH_TILE;
#pragma unroll
        for (int ks = 0; ks < 4; ks++) {
            const int cbase = 2 * ks + csel;
            uint32_t a[4][4];
#pragma unroll
            for (int i = 0; i < 4; i++)
                ldsm_x4(a[i][0], a[i][1], a[i][2], a[i][3],
                        aBuf + rowA[i] * 128 + ((cbase ^ qa[i]) << 4));
            uint32_t b[4][2];
            ldsm_x4(b[0][0], b[1][0], b[0][1], b[1][1],
                    bBuf + rowB[0] * 128 + ((cbase ^ qb[0]) << 4));
            ldsm_x4(b[2][0], b[3][0], b[2][1], b[3][1],
                    bBuf + rowB[1] * 128 + ((cbase ^ qb[1]) << 4));
#pragma unroll
            for (int i = 0; i < 4; i++)
#pragma unroll
                for (int j = 0; j < 4; j++)
                    mma_f16(c[i][j][0], c[i][j][1], c[i][j][2], c[i][j][3],
                            a[i][0], a[i][1], a[i][2], a[i][3], b[j][0], b[j][1]);
        }
        __syncthreads();
    }

    if (MODE == 3 && z == 2) {
        __half* sT = (__half*)smem;             // 128 x 136 halves
#pragma unroll
        for (int i = 0; i < 4; i++) {
            int r0l = warpM * 64 + i * 16 + gid;
#pragma unroll
            for (int j = 0; j < 4; j++) {
                int cl = warpN * 32 + j * 8 + tig * 2;
                sT[(cl)     * 136 + r0l]     = __float2half_rn(c[i][j][0]);
                sT[(cl + 1) * 136 + r0l]     = __float2half_rn(c[i][j][1]);
                sT[(cl)     * 136 + r0l + 8] = __float2half_rn(c[i][j][2]);
                sT[(cl + 1) * 136 + r0l + 8] = __float2half_rn(c[i][j][3]);
            }
        }
        __syncthreads();
        const int b = m0 / SS;
        const int s0 = m0 % SS;
        const int h = n0 / HD;
        __half* vt = g_vt + ((size_t)(b * NH + h)) * HD * SS;
#pragma unroll
        for (int it = 0; it < 8; it++) {
            int flat = it * 256 + tid;
            int hd = flat >> 4;
            int ch = flat & 15;
            *(uint4*)&vt[(size_t)hd * SS + s0 + ch * 8] =
                *(const uint4*)&sT[hd * 136 + ch * 8];
        }
        return;
    }

#pragma unroll
    for (int i = 0; i < 4; i++) {
        int row0 = m0 + warpM * 64 + i * 16 + gid;
#pragma unroll
        for (int j = 0; j < 4; j++) {
            int col = n0 + warpN * 32 + j * 8 + tig * 2;
            if (MODE == 3) {
                __half* C = (z == 0) ? g_q : g_k;
                *(uint32_t*)&C[(size_t)row0 * GN + col] = pack_h2(c[i][j][0], c[i][j][1]);
                *(uint32_t*)&C[(size_t)(row0 + 8) * GN + col] = pack_h2(c[i][j][2], c[i][j][3]);
            } else {
                float* C = (float*)Cout;
                *(float2*)&C[(size_t)row0 * GN + col] = make_float2(c[i][j][0], c[i][j][1]);
                *(float2*)&C[(size_t)(row0 + 8) * GN + col] = make_float2(c[i][j][2], c[i][j][3]);
            }
        }
    }
}

// ---------------------------------------------------------------------------
// RoPE on g_q/g_k in place. One thread per (b,s,pair): 1 sincosf, 16 heads.
// ---------------------------------------------------------------------------
__global__ __launch_bounds__(256) void rope_kernel(const int* __restrict__ pos_ids) {
    int idx = blockIdx.x * blockDim.x + threadIdx.x;
    const int total = BB * SS * (HD / 2);
    if (idx >= total) return;
    int i = idx & 63;
    int t = idx >> 6;
    int s = t & (SS - 1);
    int b = t >> 11;

    int p = pos_ids[(size_t)b * SS + s];
    float inv_freq = 1.0f / powf(10000.0f, (float)(2 * i) / (float)HD);
    float ang = (float)p * inv_freq;
    float c, sn;
    sincosf(ang, &sn, &c);

    size_t base = ((size_t)(b * SS + s) * HH) + 2 * i;
#pragma unroll
    for (int h = 0; h < NH; h++) {
        size_t a = base + (size_t)h * HD;
        __half2 q = *(__half2*)&g_q[a];
        float x1 = __low2float(q), x2 = __high2float(q);
        *(__half2*)&g_q[a] = __floats2half2_rn(x1 * c - x2 * sn, x1 * sn + x2 * c);
        __half2 k = *(__half2*)&g_k[a];
        x1 = __low2float(k); x2 = __high2float(k);
        *(__half2*)&g_k[a] = __floats2half2_rn(x1 * c - x2 * sn, x1 * sn + x2 * c);
    }
}

// ---------------------------------------------------------------------------
// FP16 tensor flash attention. BM=BN=64, 4 warps; ldmatrix fragment loads;
// causal-balanced qt remap; K/Vt cp.async double-buffered.
// ---------------------------------------------------------------------------
#define FQ_STR 136
#define FP_STR 72
#define FV_STR 72
#define FQ_OFF 0
#define FP_OFF (64 * FQ_STR)
#define FK_OFF (64 * FQ_STR + 64 * FP_STR)
#define FK_SZ  (64 * FQ_STR)
#define FV_OFF (FK_OFF + 2 * FK_SZ)
#define FV_SZ  (128 * FV_STR)
#define FLASH_SMEM_HALVES (FV_OFF + 2 * FV_SZ)

__global__ __launch_bounds__(128) void flash_f16_kernel() {
    extern __shared__ __half sh[];
    __half* sQ = sh + FQ_OFF;
    __half* sP = sh + FP_OFF;
    const uint32_t sbase = (uint32_t)__cvta_generic_to_shared(sh);

    const int tid = threadIdx.x;
    const int lane = tid & 31;
    const int warp = tid >> 5;
    const int gid = lane >> 2;
    const int tig = lane & 3;
    const int bidx = blockIdx.x;
    const int qt = (bidx & 1) ? (31 - (bidx >> 1)) : (bidx >> 1);   // balance
    const int h  = blockIdx.y;
    const int b  = blockIdx.z;
    const int qbase = qt * 64;

    const __half* qp = g_q + ((size_t)b * SS) * HH + (size_t)h * HD;
    const __half* kp = g_k + ((size_t)b * SS) * HH + (size_t)h * HD;
    const __half* vtp = g_vt + ((size_t)(b * NH + h)) * HD * SS;

    const int r0 = warp * 16 + gid;
    const int r1 = r0 + 8;

    // ldmatrix lane geometry (same mapping as gemm)
    const int lm   = lane >> 3;
    const int rsub = (lm & 1) * 8 + (lane & 7);
    const int csel = lm >> 1;                     // 0/1 -> k-chunk lo/hi (8 halves)
    const int rA = warp * 16 + rsub;              // A-frag row (Q and P)
    const uint32_t qAddrBase = sbase + (uint32_t)(rA * FQ_STR + csel * 8) * 2;
    const uint32_t pAddrBase = sbase + (uint32_t)(FP_OFF + rA * FP_STR + csel * 8) * 2;

    auto issue_kv = [&](int buf, int jt) {
        const int jbase = jt * 64;
        __half* dK = sh + FK_OFF + buf * FK_SZ;
        __half* dV = sh + FV_OFF + buf * FV_SZ;
#pragma unroll
        for (int it = 0; it < 8; it++) {
            int flat = it * 128 + tid;
            int row = flat >> 4;
            int ch = flat & 15;
            uint32_t da = (uint32_t)__cvta_generic_to_shared(&dK[row * FQ_STR + ch * 8]);
            const __half* pk = &kp[(size_t)(jbase + row) * HH + ch * 8];
            asm volatile("cp.async.cg.shared.global [%0], [%1], 16;" :: "r"(da), "l"(pk));
            int vrow = flat >> 3;
            int vch = flat & 7;
            uint32_t dv = (uint32_t)__cvta_generic_to_shared(&dV[vrow * FV_STR + vch * 8]);
            const __half* pv = &vtp[(size_t)vrow * SS + jbase + vch * 8];
            asm volatile("cp.async.cg.shared.global [%0], [%1], 16;" :: "r"(dv), "l"(pv));
        }
        asm volatile("cp.async.commit_group;");
    };

#pragma unroll
    for (int it = 0; it < 8; it++) {
        int flat = it * 128 + tid;
        int row = flat >> 4;
        int ch = flat & 15;
        *(uint4*)&sQ[row * FQ_STR + ch * 8] =
            *(const uint4*)&qp[(size_t)(qbase + row) * HH + ch * 8];
    }
    issue_kv(0, 0);

    float o[16][4];
#pragma unroll
    for (int j = 0; j < 16; j++)
#pragma unroll
        for (int r = 0; r < 4; r++) o[j][r] = 0.0f;
    float m0 = -CUDART_INF_F, m1 = -CUDART_INF_F;
    float l0 = 0.0f, l1 = 0.0f;

    for (int jt = 0; jt <= qt; jt++) {
        const int jbase = jt * 64;
        const int buf = jt & 1;
        if (jt < qt) {
            issue_kv(buf ^ 1, jt + 1);
            asm volatile("cp.async.wait_group 1;");
        } else {
            asm volatile("cp.async.wait_group 0;");
        }
        __syncthreads();
        const uint32_t kBuf = sbase + (uint32_t)(FK_OFF + buf * FK_SZ) * 2;
        const uint32_t vBuf = sbase + (uint32_t)(FV_OFF + buf * FV_SZ) * 2;

        // ---- scores S = Q K^T : 8 k-steps of 16, ldmatrix frags ----
        float s[8][4];
#pragma unroll
        for (int j = 0; j < 8; j++)
#pragma unroll
            for (int r = 0; r < 4; r++) s[j][r] = 0.0f;
#pragma unroll
        for (int ks = 0; ks < 8; ks++) {
            const int k0 = ks * 16;
            uint32_t a0, a1, a2, a3;
            ldsm_x4(a0, a1, a2, a3, qAddrBase + (uint32_t)k0 * 2);
            uint32_t bb[8][2];
#pragma unroll
            for (int jj = 0; jj < 4; jj++) {
                int rowK = jj * 16 + rsub;
                ldsm_x4(bb[2 * jj][0], bb[2 * jj + 1][0], bb[2 * jj][1], bb[2 * jj + 1][1],
                        kBuf + (uint32_t)(rowK * FQ_STR + k0 + csel * 8) * 2);
            }
#pragma unroll
            for (int j = 0; j < 8; j++)
                mma_f16(s[j][0], s[j][1], s[j][2], s[j][3], a0, a1, a2, a3,
                        bb[j][0], bb[j][1]);
        }

        // ---- scale + causal mask ----
        const bool diag = (jt == qt);
#pragma unroll
        for (int j = 0; j < 8; j++) {
            int col = jbase + j * 8 + tig * 2;
            s[j][0] *= d_scale; s[j][1] *= d_scale;
            s[j][2] *= d_scale; s[j][3] *= d_scale;
            if (diag) {
                int rg0 = qbase + r0, rg1 = qbase + r1;
                if (col     > rg0) s[j][0] = -1e30f;
                if (col + 1 > rg0) s[j][1] = -1e30f;
                if (col     > rg1) s[j][2] = -1e30f;
                if (col + 1 > rg1) s[j][3] = -1e30f;
            }
        }

        // ---- online softmax ----
        float mx0 = -CUDART_INF_F, mx1 = -CUDART_INF_F;
#pragma unroll
        for (int j = 0; j < 8; j++) {
            mx0 = fmaxf(mx0, fmaxf(s[j][0], s[j][1]));
            mx1 = fmaxf(mx1, fmaxf(s[j][2], s[j][3]));
        }
        mx0 = fmaxf(mx0, __shfl_xor_sync(0xffffffffu, mx0, 1));
        mx0 = fmaxf(mx0, __shfl_xor_sync(0xffffffffu, mx0, 2));
        mx1 = fmaxf(mx1, __shfl_xor_sync(0xffffffffu, mx1, 1));
        mx1 = fmaxf(mx1, __shfl_xor_sync(0xffffffffu, mx1, 2));
        float mn0 = fmaxf(m0, mx0), mn1 = fmaxf(m1, mx1);
        float al0 = __expf(m0 - mn0), al1 = __expf(m1 - mn1);
        float rs0 = 0.0f, rs1 = 0.0f;
#pragma unroll
        for (int j = 0; j < 8; j++) {
            s[j][0] = __expf(s[j][0] - mn0);
            s[j][1] = __expf(s[j][1] - mn0);
            s[j][2] = __expf(s[j][2] - mn1);
            s[j][3] = __expf(s[j][3] - mn1);
            rs0 += s[j][0] + s[j][1];
            rs1 += s[j][2] + s[j][3];
        }
        rs0 += __shfl_xor_sync(0xffffffffu, rs0, 1);
        rs0 += __shfl_xor_sync(0xffffffffu, rs0, 2);
        rs1 += __shfl_xor_sync(0xffffffffu, rs1, 1);
        rs1 += __shfl_xor_sync(0xffffffffu, rs1, 2);
        l0 = l0 * al0 + rs0;  m0 = mn0;
        l1 = l1 * al1 + rs1;  m1 = mn1;
#pragma unroll
        for (int j = 0; j < 16; j++) {
            o[j][0] *= al0; o[j][1] *= al0;
            o[j][2] *= al1; o[j][3] *= al1;
        }
#pragma unroll
        for (int j = 0; j < 8; j++) {
            int col = j * 8 + tig * 2;
            *(uint32_t*)&sP[r0 * FP_STR + col] = pack_h2(s[j][0], s[j][1]);
            *(uint32_t*)&sP[r1 * FP_STR + col] = pack_h2(s[j][2], s[j][3]);
        }
        __syncwarp();

        // ---- O += P @ V : 4 k-steps of 16, ldmatrix frags ----
#pragma unroll
        for (int ks = 0; ks < 4; ks++) {
            const int k0 = ks * 16;
            uint32_t a0, a1, a2, a3;
            ldsm_x4(a0, a1, a2, a3, pAddrBase + (uint32_t)k0 * 2);
#pragma unroll
            for (int jj = 0; jj < 8; jj++) {
                int rowV = jj * 16 + rsub;
                uint32_t b00, b10, b01, b11;
                ldsm_x4(b00, b10, b01, b11,
                        vBuf + (uint32_t)(rowV * FV_STR + k0 + csel * 8) * 2);
                mma_f16(o[2 * jj][0], o[2 * jj][1], o[2 * jj][2], o[2 * jj][3],
                        a0, a1, a2, a3, b00, b01);
                mma_f16(o[2 * jj + 1][0], o[2 * jj + 1][1], o[2 * jj + 1][2], o[2 * jj + 1][3],
                        a0, a1, a2, a3, b10, b11);
            }
        }
        __syncthreads();
    }

    // ---- epilogue ----
    __half* cp = g_ctx + ((size_t)b * SS) * HH + (size_t)h * HD;
    float inv0 = 1.0f / l0, inv1 = 1.0f / l1;
    size_t grow0 = (size_t)(qbase + r0) * HH;
    size_t grow1 = (size_t)(qbase + r1) * HH;
#pragma unroll
    for (int j = 0; j < 16; j++) {
        int col = j * 8 + tig * 2;
        *(uint32_t*)&cp[grow0 + col] = pack_h2(o[j][0] * inv0, o[j][1] * inv0);
        *(uint32_t*)&cp[grow1 + col] = pack_h2(o[j][2] * inv1, o[j][3] * inv1);
    }
}

// ---------------------------------------------------------------------------
extern "C" void kernel_launch(void* const* d_in, const int* in_sizes, int n_in,
                              void* d_out, int out_size) {
    const float* hidden = (const float*)d_in[0];
    const float* Wq = (const float*)d_in[1];
    const float* Wk = (const float*)d_in[2];
    const float* Wv = (const float*)d_in[3];
    const float* Wd = (const float*)d_in[4];
    const int* pos = (const int*)d_in[6];
    float* out = (float*)d_out;

    __half *cptr, *hptr, *wdp;
    cudaGetSymbolAddress((void**)&cptr, g_ctx);
    cudaGetSymbolAddress((void**)&hptr, g_hid);
    cudaGetSymbolAddress((void**)&wdp, g_wd);

    cudaFuncSetAttribute(gemm_f16<0>,
                         cudaFuncAttributeMaxDynamicSharedMemorySize, GH_SMEM);
    cudaFuncSetAttribute(gemm_f16<3>,
                         cudaFuncAttributeMaxDynamicSharedMemorySize, GH_SMEM);
    cudaFuncSetAttribute(flash_f16_kernel,
                         cudaFuncAttributeMaxDynamicSharedMemorySize,
                         FLASH_SMEM_HALVES * (int)sizeof(__half));

    int nw4 = HH * HH / 4;
    dim3 conv_grid((nw4 + 255) / 256, 1, 6);
    conv_all_kernel<<<conv_grid, 256>>>((const float4*)hidden, (const float4*)Wq,
                                        (const float4*)Wk, (const float4*)Wv,
                                        (const float4*)Wd, nw4);

    dim3 qkv_grid(HH / 128, MTOT / 128, 3);
    gemm_f16<3><<<qkv_grid, 256, GH_SMEM>>>(hptr, nullptr, nullptr);

    int rope_total = BB * SS * (HD / 2);
    rope_kernel<<<(rope_total + 255) / 256, 256>>>(pos);

    dim3 flash_grid(SS / 64, NH, BB);
    flash_f16_kernel<<<flash_grid, 128, FLASH_SMEM_HALVES * sizeof(__half)>>>();

    dim3 gemm_grid(HH / 128, MTOT / 128);
    gemm_f16<0><<<gemm_grid, 256, GH_SMEM>>>(cptr, wdp, out);
}